// round 11
// baseline (speedup 1.0000x reference)
#include <cuda_runtime.h>

#define F   16
#define HID 64
#define NN  100000
#define EE  3200000
#define ROUNDS 5

typedef unsigned long long ull;

__device__ __align__(256) float g_edges[(size_t)EE * F];   // [E][F] internal layout
__device__ __align__(256) float g_nodes[F * NN];           // [F][N]
__device__ __align__(256) float g_sent[NN * F];            // [N][F]
__device__ __align__(256) float g_recv[NN * F];            // [N][F]
__device__ __align__(256) float g_ps[NN * HID];            // [N][HID]  eW1_s @ nodes + eb1
__device__ __align__(256) float g_pr[NN * HID];            // [N][HID]  eW1_r @ nodes

// pre-transposed edge-MLP weights (smem-layout-identical, loaded linearly)
#define W1_FLOATS (16 * 68)            // [k][68]: half0 h at k*68+h, half1 at k*68+4+h
#define W2_FLOATS (2 * 32 * 16 + 4)    // half0 rows at 0, half1 rows at 516
__device__ __align__(256) float g_w1p[W1_FLOATS];
__device__ __align__(256) float g_w2p[W2_FLOATS];
__device__ __align__(256) float g_b2p[16];

// pre-transposed node-MLP + projection weights
__device__ __align__(256) float g_nw1t[48 * HID];   // [k][h]
__device__ __align__(256) float g_nw2t[HID * F];    // [h][o]
__device__ __align__(256) float g_nws[16 * HID];    // eW1 cols 16..31, [k][h]
__device__ __align__(256) float g_nwr[16 * HID];    // eW1 cols 32..47, [k][h]
__device__ __align__(256) float g_nb1[HID];
__device__ __align__(256) float g_nb2[F];
__device__ __align__(256) float g_neb1[HID];

__device__ __forceinline__ ull pack2(float a, float b) {
    ull r; asm("mov.b64 %0, {%1,%2};" : "=l"(r) : "f"(a), "f"(b)); return r;
}
__device__ __forceinline__ void unpack2(ull v, float& a, float& b) {
    asm("mov.b64 {%0,%1}, %2;" : "=f"(a), "=f"(b) : "l"(v));
}
__device__ __forceinline__ ull fma2(ull a, ull b, ull c) {
    ull d; asm("fma.rn.f32x2 %0, %1, %2, %3;" : "=l"(d) : "l"(a), "l"(b), "l"(c)); return d;
}
__device__ __forceinline__ ull add2(ull a, ull b) {
    ull d; asm("add.rn.f32x2 %0, %1, %2;" : "=l"(d) : "l"(a), "l"(b)); return d;
}

// one-time: transpose ALL weights into kernel-friendly layouts
__global__ void prep_weights_kernel(const float* __restrict__ eW1,
                                    const float* __restrict__ eW2,
                                    const float* __restrict__ eb2,
                                    const float* __restrict__ nW1,
                                    const float* __restrict__ nb1,
                                    const float* __restrict__ nW2,
                                    const float* __restrict__ nb2,
                                    const float* __restrict__ eb1) {
    int tid = threadIdx.x;
    for (int i = tid; i < 16 * 64; i += blockDim.x) {
        int k = i >> 6, h = i & 63;
        g_w1p[k * 68 + h + (h >= 32 ? 4 : 0)] = eW1[h * 48 + k];
        g_nws[k * HID + h] = eW1[h * 48 + 16 + k];
        g_nwr[k * HID + h] = eW1[h * 48 + 32 + k];
    }
    for (int i = tid; i < 64 * 16; i += blockDim.x) {
        int h = i >> 4, o = i & 15;
        g_w2p[(h < 32) ? (h * 16 + o) : (516 + (h - 32) * 16 + o)] = eW2[o * 64 + h];
        g_nw2t[h * F + o] = nW2[o * HID + h];
    }
    for (int i = tid; i < 48 * 64; i += blockDim.x) {
        int k = i >> 6, h = i & 63;
        g_nw1t[k * HID + h] = nW1[h * 48 + k];
    }
    if (tid < 16) { g_b2p[tid] = eb2[tid]; g_nb2[tid] = nb2[tid]; }
    if (tid < HID) { g_nb1[tid] = nb1[tid]; g_neb1[tid] = eb1[tid]; }
}

__global__ void zero_agg_kernel() {
    int i = blockIdx.x * blockDim.x + threadIdx.x;
    const int n4 = (NN * F) / 4;
    float4 z = make_float4(0.f, 0.f, 0.f, 0.f);
    if (i < n4) {
        reinterpret_cast<float4*>(g_sent)[i] = z;
        reinterpret_cast<float4*>(g_recv)[i] = z;
    }
}

// round-0 scatter (cooperative red): reads the ORIGINAL [F][E] input edges
#define STPB 256
#define SV_STRIDE 20
__global__ void __launch_bounds__(STPB)
scatter_kernel(const float* __restrict__ edges,
               const int* __restrict__ snd, const int* __restrict__ rcv) {
    __shared__ __align__(16) float s_v[STPB * SV_STRIDE];
    const int tid = threadIdx.x;
    const int e0 = blockIdx.x * STPB;
    const size_t e = (size_t)e0 + tid;

    float v[F];
#pragma unroll
    for (int f = 0; f < F; f++) v[f] = __ldcs(&edges[(size_t)f * EE + e]);
#pragma unroll
    for (int q = 0; q < 4; q++) {
        float4 w = make_float4(v[q * 4], v[q * 4 + 1], v[q * 4 + 2], v[q * 4 + 3]);
        *reinterpret_cast<float4*>(&s_v[tid * SV_STRIDE + q * 4]) = w;
    }
    __syncthreads();
    // 256 threads x 8 ops = 256 edges x 2 targets x 4 chunks; 4 lanes/row -> 1 line
#pragma unroll
    for (int p = 0; p < 8; p++) {
        int g = tid + p * STPB;
        int chunk = g & 3;
        int which = (g >> 2) & 1;
        int el    = g >> 3;
        int node  = which ? rcv[e0 + el] : snd[e0 + el];
        float* base = which ? g_recv : g_sent;
        float4 w = *reinterpret_cast<const float4*>(&s_v[el * SV_STRIDE + chunk * 4]);
        asm volatile("red.global.add.v4.f32 [%0], {%1,%2,%3,%4};"
                     :: "l"(base + (size_t)node * F + chunk * 4),
                        "f"(w.x), "f"(w.y), "f"(w.z), "f"(w.w)
                     : "memory");
    }
}

// fused node MLP + edge projections + aggregate re-zeroing (prepped weights)
__global__ void __launch_bounds__(256)
node_proj_kernel(const float* src_nodes_in, float* out_nodes) {
    const float* __restrict__ src_nodes = src_nodes_in ? src_nodes_in : g_nodes;
    __shared__ __align__(16) float s_w1t[48 * HID];
    __shared__ __align__(16) float s_w2t[HID * F];
    __shared__ __align__(16) float s_ws[16 * HID];
    __shared__ __align__(16) float s_wr[16 * HID];
    __shared__ __align__(16) float s_b1[HID];
    __shared__ __align__(16) float s_b2[F];
    __shared__ __align__(16) float s_eb1[HID];
    {
        const float4* src;
        float4* dst;
        src = reinterpret_cast<const float4*>(g_nw1t); dst = reinterpret_cast<float4*>(s_w1t);
        for (int i = threadIdx.x; i < (48 * HID) / 4; i += blockDim.x) dst[i] = src[i];
        src = reinterpret_cast<const float4*>(g_nw2t); dst = reinterpret_cast<float4*>(s_w2t);
        for (int i = threadIdx.x; i < (HID * F) / 4; i += blockDim.x) dst[i] = src[i];
        src = reinterpret_cast<const float4*>(g_nws); dst = reinterpret_cast<float4*>(s_ws);
        for (int i = threadIdx.x; i < (16 * HID) / 4; i += blockDim.x) dst[i] = src[i];
        src = reinterpret_cast<const float4*>(g_nwr); dst = reinterpret_cast<float4*>(s_wr);
        for (int i = threadIdx.x; i < (16 * HID) / 4; i += blockDim.x) dst[i] = src[i];
        if (threadIdx.x < HID) { s_b1[threadIdx.x] = g_nb1[threadIdx.x]; s_eb1[threadIdx.x] = g_neb1[threadIdx.x]; }
        if (threadIdx.x < F)   s_b2[threadIdx.x] = g_nb2[threadIdx.x];
    }
    __syncthreads();

    int n = blockIdx.x * blockDim.x + threadIdx.x;
    if (n >= NN) return;

    ull acc[HID / 2];
#pragma unroll
    for (int j = 0; j < HID / 4; j++) {
        ulonglong2 bv = *reinterpret_cast<const ulonglong2*>(&s_b1[j * 4]);
        acc[2 * j] = bv.x; acc[2 * j + 1] = bv.y;
    }
#pragma unroll
    for (int k = 0; k < 16; k++) {
        float xk = src_nodes[(size_t)k * NN + n];
        ull xs = pack2(xk, xk);
        const ulonglong2* w = reinterpret_cast<const ulonglong2*>(&s_w1t[k * HID]);
#pragma unroll
        for (int m = 0; m < 16; m++) {
            ulonglong2 wv = w[m];
            acc[2 * m]     = fma2(wv.x, xs, acc[2 * m]);
            acc[2 * m + 1] = fma2(wv.y, xs, acc[2 * m + 1]);
        }
    }
    const float4 zero4 = make_float4(0.f, 0.f, 0.f, 0.f);
#pragma unroll
    for (int seg = 0; seg < 2; seg++) {
        float* aggr = seg == 0 ? &g_sent[(size_t)n * F] : &g_recv[(size_t)n * F];
        float xv[16];
#pragma unroll
        for (int q = 0; q < 4; q++) {
            float4 v = *reinterpret_cast<const float4*>(&aggr[q * 4]);
            xv[q * 4] = v.x; xv[q * 4 + 1] = v.y; xv[q * 4 + 2] = v.z; xv[q * 4 + 3] = v.w;
            *reinterpret_cast<float4*>(&aggr[q * 4]) = zero4;  // re-zero for next round
        }
#pragma unroll
        for (int k = 0; k < 16; k++) {
            ull xs = pack2(xv[k], xv[k]);
            const ulonglong2* w = reinterpret_cast<const ulonglong2*>(&s_w1t[((seg + 1) * 16 + k) * HID]);
#pragma unroll
            for (int m = 0; m < 16; m++) {
                ulonglong2 wv = w[m];
                acc[2 * m]     = fma2(wv.x, xs, acc[2 * m]);
                acc[2 * m + 1] = fma2(wv.y, xs, acc[2 * m + 1]);
            }
        }
    }

    ull o[F / 2];
#pragma unroll
    for (int j = 0; j < 4; j++) {
        ulonglong2 bv = *reinterpret_cast<const ulonglong2*>(&s_b2[j * 4]);
        o[2 * j] = bv.x; o[2 * j + 1] = bv.y;
    }
#pragma unroll
    for (int h = 0; h < HID; h += 2) {
        float h0, h1; unpack2(acc[h >> 1], h0, h1);
        h0 = fmaxf(h0, 0.f); h1 = fmaxf(h1, 0.f);
        ull x0 = pack2(h0, h0), x1 = pack2(h1, h1);
        const ulonglong2* w0 = reinterpret_cast<const ulonglong2*>(&s_w2t[h * F]);
        const ulonglong2* w1 = reinterpret_cast<const ulonglong2*>(&s_w2t[(h + 1) * F]);
#pragma unroll
        for (int m = 0; m < 4; m++) {
            ulonglong2 a = w0[m], b = w1[m];
            o[2 * m]     = fma2(a.x, x0, o[2 * m]);
            o[2 * m]     = fma2(b.x, x1, o[2 * m]);
            o[2 * m + 1] = fma2(a.y, x0, o[2 * m + 1]);
            o[2 * m + 1] = fma2(b.y, x1, o[2 * m + 1]);
        }
    }
    float y[F];
#pragma unroll
    for (int j = 0; j < F / 2; j++) unpack2(o[j], y[2 * j], y[2 * j + 1]);
#pragma unroll
    for (int k = 0; k < F; k++) {
        g_nodes[(size_t)k * NN + n] = y[k];
    }
    if (out_nodes) {
#pragma unroll
        for (int k = 0; k < F; k++) out_nodes[(size_t)k * NN + n] = y[k];
    }

#pragma unroll
    for (int j = 0; j < HID / 4; j++) {
        ulonglong2 bv = *reinterpret_cast<const ulonglong2*>(&s_eb1[j * 4]);
        acc[2 * j] = bv.x; acc[2 * j + 1] = bv.y;
    }
#pragma unroll
    for (int k = 0; k < 16; k++) {
        ull xs = pack2(y[k], y[k]);
        const ulonglong2* w = reinterpret_cast<const ulonglong2*>(&s_ws[k * HID]);
#pragma unroll
        for (int m = 0; m < 16; m++) {
            ulonglong2 wv = w[m];
            acc[2 * m]     = fma2(wv.x, xs, acc[2 * m]);
            acc[2 * m + 1] = fma2(wv.y, xs, acc[2 * m + 1]);
        }
    }
    ull* outp = reinterpret_cast<ull*>(&g_ps[(size_t)n * HID]);
#pragma unroll
    for (int j = 0; j < HID / 2; j++) outp[j] = acc[j];

#pragma unroll
    for (int j = 0; j < HID / 2; j++) acc[j] = 0ull;
#pragma unroll
    for (int k = 0; k < 16; k++) {
        ull xs = pack2(y[k], y[k]);
        const ulonglong2* w = reinterpret_cast<const ulonglong2*>(&s_wr[k * HID]);
#pragma unroll
        for (int m = 0; m < 16; m++) {
            ulonglong2 wv = w[m];
            acc[2 * m]     = fma2(wv.x, xs, acc[2 * m]);
            acc[2 * m + 1] = fma2(wv.y, xs, acc[2 * m + 1]);
        }
    }
    outp = reinterpret_cast<ull*>(&g_pr[(size_t)n * HID]);
#pragma unroll
    for (int j = 0; j < HID / 2; j++) outp[j] = acc[j];
}

// ---------------- edge MLP v8: v7 + sequential layer-2 + 4 CTAs/SM -----------
#define ETPB 128
#define EPB  128
#define SG_STRIDE 72   // gather row: halves at +0 / +36; also reused as s_out (stride 20)
#define SX_STRIDE 34   // x row per PAIR: [k*2 + half]
#define SO_STRIDE 20   // ov row in reused s_g
#define SG_FLOATS (EPB * SG_STRIDE)
#define SX_FLOATS ((EPB / 2) * SX_STRIDE)
#define EDGE_SMEM_FLOATS (SG_FLOATS + SX_FLOATS + W1_FLOATS + W2_FLOATS + 16)

__global__ void __launch_bounds__(ETPB, 4)
edge_mlp_kernel(const float* src_fe, float* dst_fe,
                const int* __restrict__ snd, const int* __restrict__ rcv,
                int do_scatter) {
    extern __shared__ __align__(16) float smem[];
    float* s_g  = smem;                          // EPB x 72 (split halves); reused as s_out
    float* s_x  = s_g + SG_FLOATS;               // (EPB/2) x 34
    float* s_w1 = s_x + SX_FLOATS;               // 16 x 68 (split halves)
    float* s_w2 = s_w1 + W1_FLOATS;              // 1028 (split at 516)
    float* s_b2 = s_w2 + W2_FLOATS;              // 16

    const int tid  = threadIdx.x;
    const int half = tid & 1;                    // hidden half: h in [32*half, 32*half+32)
    const int pair = tid >> 1;                   // local pair index
    const int e0   = blockIdx.x * EPB;
    const int ee_l = tid & ~1;                   // even local edge of my pair
    const size_t em = (size_t)e0 + tid;          // my OUTPUT edge

    // ---- load my edge's features (coalesced), stage x into smem
    {
        float x[16];
        if (src_fe) {
#pragma unroll
            for (int k = 0; k < 16; k++) x[k] = __ldcs(&src_fe[(size_t)k * EE + em]);
        } else {
#pragma unroll
            for (int q = 0; q < 4; q++) {
                float4 v = __ldcs(reinterpret_cast<const float4*>(&g_edges[em * F + q * 4]));
                x[q * 4] = v.x; x[q * 4 + 1] = v.y; x[q * 4 + 2] = v.z; x[q * 4 + 3] = v.w;
            }
        }
#pragma unroll
        for (int k = 0; k < 16; k++) s_x[pair * SX_STRIDE + 2 * k + half] = x[k];
    }

    // ---- weights: LINEAR float4 loads from pre-transposed globals (L2-hot)
    {
        const float4* w1s = reinterpret_cast<const float4*>(g_w1p);
        float4*       w1d = reinterpret_cast<float4*>(s_w1);
        for (int i = tid; i < W1_FLOATS / 4; i += ETPB) w1d[i] = w1s[i];
        const float4* w2s = reinterpret_cast<const float4*>(g_w2p);
        float4*       w2d = reinterpret_cast<float4*>(s_w2);
        for (int i = tid; i < W2_FLOATS / 4; i += ETPB) w2d[i] = w2s[i];
        if (tid < 16) s_b2[tid] = g_b2p[tid];
    }

    // ---- cooperative gather staging into split rows
    {
        const int wid  = tid >> 5;        // 4 warps, 32 edges each
        const int lane = tid & 31;
        const int sub  = lane >> 4;
        const int c    = lane & 15;
        const int coff = c * 4 + (c >= 8 ? 4 : 0);
#pragma unroll
        for (int i = 0; i < 32; i += 2) {
            int el = wid * 32 + i + sub;
            int s = snd[e0 + el];
            int r = rcv[e0 + el];
            ulonglong2 a = *reinterpret_cast<const ulonglong2*>(&g_ps[(size_t)s * HID + c * 4]);
            ulonglong2 b = *reinterpret_cast<const ulonglong2*>(&g_pr[(size_t)r * HID + c * 4]);
            ulonglong2 v; v.x = add2(a.x, b.x); v.y = add2(a.y, b.y);
            *reinterpret_cast<ulonglong2*>(&s_g[el * SG_STRIDE + coff]) = v;
        }
    }
    __syncthreads();

    // ---- layer-1 accumulators: my half of BOTH edges (eb1 folded in g_ps)
    ull acc0[16], acc1[16];   // acc0: edge ee_l, acc1: edge ee_l+1
    {
        const ulonglong2* g0 = reinterpret_cast<const ulonglong2*>(&s_g[ee_l * SG_STRIDE + half * 36]);
        const ulonglong2* g1 = reinterpret_cast<const ulonglong2*>(&s_g[(ee_l + 1) * SG_STRIDE + half * 36]);
#pragma unroll
        for (int m = 0; m < 8; m++) {
            ulonglong2 v = g0[m]; acc0[2 * m] = v.x; acc0[2 * m + 1] = v.y;
            ulonglong2 u = g1[m]; acc1[2 * m] = u.x; acc1[2 * m + 1] = u.y;
        }
    }

    // ---- layer 1: one LDS.64 per k gives both edges' x; weights shared
#pragma unroll
    for (int k = 0; k < 16; k++) {
        float2 xp = *reinterpret_cast<const float2*>(&s_x[pair * SX_STRIDE + 2 * k]);
        ull xs0 = pack2(xp.x, xp.x);     // edge ee_l
        ull xs1 = pack2(xp.y, xp.y);     // edge ee_l+1
        const ulonglong2* w = reinterpret_cast<const ulonglong2*>(&s_w1[k * 68 + half * 36]);
#pragma unroll
        for (int m = 0; m < 8; m++) {
            ulonglong2 wv = w[m];
            acc0[2 * m]     = fma2(wv.x, xs0, acc0[2 * m]);
            acc0[2 * m + 1] = fma2(wv.y, xs0, acc0[2 * m + 1]);
            acc1[2 * m]     = fma2(wv.x, xs1, acc1[2 * m]);
            acc1[2 * m + 1] = fma2(wv.y, xs1, acc1[2 * m + 1]);
        }
    }

    // ---- layer 2, SEQUENTIAL per edge (halves register pressure):
    //      phase A: edge ee_l from acc0 (both lanes) -> full sum lands everywhere,
    //      lane keeps it if it owns that edge; phase B: edge ee_l+1 from acc1.
    const float* w2b = s_w2 + (half ? 516 : 0);
    float ov[16];

#pragma unroll
    for (int phase = 0; phase < 2; phase++) {
        ull o[8];
        if (half == 0) {
#pragma unroll
            for (int j = 0; j < 4; j++) {
                ulonglong2 bv = *reinterpret_cast<const ulonglong2*>(&s_b2[j * 4]);
                o[2 * j] = bv.x; o[2 * j + 1] = bv.y;
            }
        } else {
#pragma unroll
            for (int j = 0; j < 8; j++) o[j] = 0ull;
        }
#pragma unroll
        for (int it = 0; it < 16; it++) {
            ull a_it = phase == 0 ? acc0[it] : acc1[it];
            float a0, a1; unpack2(a_it, a0, a1);
            a0 = fmaxf(a0, 0.f); a1 = fmaxf(a1, 0.f);
            ull p0 = pack2(a0, a0), p1 = pack2(a1, a1);
            const ulonglong2* w0 = reinterpret_cast<const ulonglong2*>(&w2b[(2 * it) * 16]);
            const ulonglong2* w1 = reinterpret_cast<const ulonglong2*>(&w2b[(2 * it + 1) * 16]);
#pragma unroll
            for (int m = 0; m < 4; m++) {
                ulonglong2 a = w0[m], b = w1[m];
                o[2 * m]     = fma2(a.x, p0, o[2 * m]);
                o[2 * m]     = fma2(b.x, p1, o[2 * m]);
                o[2 * m + 1] = fma2(a.y, p0, o[2 * m + 1]);
                o[2 * m + 1] = fma2(b.y, p1, o[2 * m + 1]);
            }
        }
        // combine halves: full result for edge (ee_l + phase)
#pragma unroll
        for (int j = 0; j < 8; j++) {
            ull rec = __shfl_xor_sync(0xFFFFFFFFu, o[j], 1);
            ull tot = add2(o[j], rec);
            if (phase == half) unpack2(tot, ov[2 * j], ov[2 * j + 1]);
        }
    }

    // ---- write my edge's new features
    if (dst_fe) {
#pragma unroll
        for (int f = 0; f < F; f++) __stcs(&dst_fe[(size_t)f * EE + em], ov[f]);
    } else {
#pragma unroll
        for (int q = 0; q < 4; q++) {
            float4 v = make_float4(ov[q * 4], ov[q * 4 + 1], ov[q * 4 + 2], ov[q * 4 + 3]);
            __stcs(reinterpret_cast<float4*>(&g_edges[em * F + q * 4]), v);
        }
    }

    // ---- cooperative red phase: 4 lanes cover one edge's 64B row -> 1 line
    if (do_scatter) {
        float* s_out = s_g;                       // staging buffer is dead; reuse
        __syncthreads();
#pragma unroll
        for (int q = 0; q < 4; q++) {
            float4 v = make_float4(ov[q * 4], ov[q * 4 + 1], ov[q * 4 + 2], ov[q * 4 + 3]);
            *reinterpret_cast<float4*>(&s_out[tid * SO_STRIDE + q * 4]) = v;
        }
        __syncthreads();
#pragma unroll
        for (int p = 0; p < 8; p++) {
            int g = tid + p * ETPB;
            int chunk = g & 3;
            int which = (g >> 2) & 1;
            int el    = g >> 3;
            int node  = which ? rcv[e0 + el] : snd[e0 + el];
            float* base = which ? g_recv : g_sent;
            float4 v = *reinterpret_cast<const float4*>(&s_out[el * SO_STRIDE + chunk * 4]);
            asm volatile("red.global.add.v4.f32 [%0], {%1,%2,%3,%4};"
                         :: "l"(base + (size_t)node * F + chunk * 4),
                            "f"(v.x), "f"(v.y), "f"(v.z), "f"(v.w)
                         : "memory");
        }
    }
}

extern "C" void kernel_launch(void* const* d_in, const int* in_sizes, int n_in,
                              void* d_out, int out_size) {
    const float* nodes     = (const float*)d_in[0];
    const float* edges     = (const float*)d_in[1];
    const int*   receivers = (const int*)  d_in[2];
    const int*   senders   = (const int*)  d_in[3];
    const float* nW1 = (const float*)d_in[4];
    const float* nb1 = (const float*)d_in[5];
    const float* nW2 = (const float*)d_in[6];
    const float* nb2 = (const float*)d_in[7];
    const float* eW1 = (const float*)d_in[8];
    const float* eb1 = (const float*)d_in[9];
    const float* eW2 = (const float*)d_in[10];
    const float* eb2 = (const float*)d_in[11];
    float* out_nodes = (float*)d_out;
    float* out_edges = (float*)d_out + (size_t)F * NN;

    const int EDGE_BLOCKS = EE / EPB;                  // 25000
    const int NODE_BLOCKS = (NN + 255) / 256;          // 391
    const int ZERO_BLOCKS = ((NN * F) / 4 + 255) / 256;
    const int EDGE_SMEM = EDGE_SMEM_FLOATS * 4;        // ~54.1 KB

    static int configured = 0;
    if (!configured) {
        cudaFuncSetAttribute(edge_mlp_kernel, cudaFuncAttributeMaxDynamicSharedMemorySize, EDGE_SMEM);
        configured = 1;
    }

    prep_weights_kernel<<<1, 256>>>(eW1, eW2, eb2, nW1, nb1, nW2, nb2, eb1);
    zero_agg_kernel<<<ZERO_BLOCKS, 256>>>();
    scatter_kernel<<<EE / STPB, STPB>>>(edges, senders, receivers);

    for (int round = 0; round < ROUNDS; round++) {
        node_proj_kernel<<<NODE_BLOCKS, 256>>>(
            (round == 0) ? nodes : (const float*)0,
            (round == ROUNDS - 1) ? out_nodes : (float*)0);
        edge_mlp_kernel<<<EDGE_BLOCKS, ETPB, EDGE_SMEM>>>(
            (round == 0) ? edges : (const float*)0,
            (round == ROUNDS - 1) ? out_edges : (float*)0,
            senders, receivers, (round < ROUNDS - 1) ? 1 : 0);
    }
}

// round 12
// speedup vs baseline: 1.1168x; 1.1168x over previous
#include <cuda_runtime.h>

#define F   16
#define HID 64
#define NN  100000
#define EE  3200000
#define ROUNDS 5

typedef unsigned long long ull;

__device__ __align__(256) float g_edges[(size_t)EE * F];   // [E][F] internal layout
__device__ __align__(256) float g_nodes[F * NN];           // [F][N]
__device__ __align__(256) float g_sent[NN * F];            // [N][F]
__device__ __align__(256) float g_recv[NN * F];            // [N][F]
__device__ __align__(256) float g_ps[NN * HID];            // [N][HID]  eW1_s @ nodes + eb1
__device__ __align__(256) float g_pr[NN * HID];            // [N][HID]  eW1_r @ nodes

// pre-transposed edge-MLP weights (smem-layout-identical, loaded linearly)
#define W1_FLOATS (16 * 68)            // [k][68]: half0 h at k*68+h, half1 at k*68+4+h
#define W2_FLOATS (2 * 32 * 16 + 4)    // half0 rows at 0, half1 rows at 516
__device__ __align__(256) float g_w1p[W1_FLOATS];
__device__ __align__(256) float g_w2p[W2_FLOATS];
__device__ __align__(256) float g_b2p[16];

// pre-transposed node-MLP + projection weights
__device__ __align__(256) float g_nw1t[48 * HID];   // [k][h]
__device__ __align__(256) float g_nw2t[HID * F];    // [h][o]
__device__ __align__(256) float g_nws[16 * HID];    // eW1 cols 16..31, [k][h]
__device__ __align__(256) float g_nwr[16 * HID];    // eW1 cols 32..47, [k][h]
__device__ __align__(256) float g_nb1[HID];
__device__ __align__(256) float g_nb2[F];
__device__ __align__(256) float g_neb1[HID];

__device__ __forceinline__ ull pack2(float a, float b) {
    ull r; asm("mov.b64 %0, {%1,%2};" : "=l"(r) : "f"(a), "f"(b)); return r;
}
__device__ __forceinline__ void unpack2(ull v, float& a, float& b) {
    asm("mov.b64 {%0,%1}, %2;" : "=f"(a), "=f"(b) : "l"(v));
}
__device__ __forceinline__ ull fma2(ull a, ull b, ull c) {
    ull d; asm("fma.rn.f32x2 %0, %1, %2, %3;" : "=l"(d) : "l"(a), "l"(b), "l"(c)); return d;
}
__device__ __forceinline__ ull add2(ull a, ull b) {
    ull d; asm("add.rn.f32x2 %0, %1, %2;" : "=l"(d) : "l"(a), "l"(b)); return d;
}

// one-time: transpose ALL weights into kernel-friendly layouts
__global__ void prep_weights_kernel(const float* __restrict__ eW1,
                                    const float* __restrict__ eW2,
                                    const float* __restrict__ eb2,
                                    const float* __restrict__ nW1,
                                    const float* __restrict__ nb1,
                                    const float* __restrict__ nW2,
                                    const float* __restrict__ nb2,
                                    const float* __restrict__ eb1) {
    int tid = threadIdx.x;
    for (int i = tid; i < 16 * 64; i += blockDim.x) {
        int k = i >> 6, h = i & 63;
        g_w1p[k * 68 + h + (h >= 32 ? 4 : 0)] = eW1[h * 48 + k];
        g_nws[k * HID + h] = eW1[h * 48 + 16 + k];
        g_nwr[k * HID + h] = eW1[h * 48 + 32 + k];
    }
    for (int i = tid; i < 64 * 16; i += blockDim.x) {
        int h = i >> 4, o = i & 15;
        g_w2p[(h < 32) ? (h * 16 + o) : (516 + (h - 32) * 16 + o)] = eW2[o * 64 + h];
        g_nw2t[h * F + o] = nW2[o * HID + h];
    }
    for (int i = tid; i < 48 * 64; i += blockDim.x) {
        int k = i >> 6, h = i & 63;
        g_nw1t[k * HID + h] = nW1[h * 48 + k];
    }
    if (tid < 16) { g_b2p[tid] = eb2[tid]; g_nb2[tid] = nb2[tid]; }
    if (tid < HID) { g_nb1[tid] = nb1[tid]; g_neb1[tid] = eb1[tid]; }
}

__global__ void zero_agg_kernel() {
    int i = blockIdx.x * blockDim.x + threadIdx.x;
    const int n4 = (NN * F) / 4;
    float4 z = make_float4(0.f, 0.f, 0.f, 0.f);
    if (i < n4) {
        reinterpret_cast<float4*>(g_sent)[i] = z;
        reinterpret_cast<float4*>(g_recv)[i] = z;
    }
}

// round-0 scatter (cooperative red): reads the ORIGINAL [F][E] input edges
#define STPB 256
#define SV_STRIDE 20
__global__ void __launch_bounds__(STPB)
scatter_kernel(const float* __restrict__ edges,
               const int* __restrict__ snd, const int* __restrict__ rcv) {
    __shared__ __align__(16) float s_v[STPB * SV_STRIDE];
    const int tid = threadIdx.x;
    const int e0 = blockIdx.x * STPB;
    const size_t e = (size_t)e0 + tid;

    float v[F];
#pragma unroll
    for (int f = 0; f < F; f++) v[f] = __ldcs(&edges[(size_t)f * EE + e]);
#pragma unroll
    for (int q = 0; q < 4; q++) {
        float4 w = make_float4(v[q * 4], v[q * 4 + 1], v[q * 4 + 2], v[q * 4 + 3]);
        *reinterpret_cast<float4*>(&s_v[tid * SV_STRIDE + q * 4]) = w;
    }
    __syncthreads();
#pragma unroll
    for (int p = 0; p < 8; p++) {
        int g = tid + p * STPB;
        int chunk = g & 3;
        int which = (g >> 2) & 1;
        int el    = g >> 3;
        int node  = which ? rcv[e0 + el] : snd[e0 + el];
        float* base = which ? g_recv : g_sent;
        float4 w = *reinterpret_cast<const float4*>(&s_v[el * SV_STRIDE + chunk * 4]);
        asm volatile("red.global.add.v4.f32 [%0], {%1,%2,%3,%4};"
                     :: "l"(base + (size_t)node * F + chunk * 4),
                        "f"(w.x), "f"(w.y), "f"(w.z), "f"(w.w)
                     : "memory");
    }
}

// fused node MLP + edge projections + aggregate re-zeroing (prepped weights)
__global__ void __launch_bounds__(256)
node_proj_kernel(const float* src_nodes_in, float* out_nodes) {
    const float* __restrict__ src_nodes = src_nodes_in ? src_nodes_in : g_nodes;
    __shared__ __align__(16) float s_w1t[48 * HID];
    __shared__ __align__(16) float s_w2t[HID * F];
    __shared__ __align__(16) float s_ws[16 * HID];
    __shared__ __align__(16) float s_wr[16 * HID];
    __shared__ __align__(16) float s_b1[HID];
    __shared__ __align__(16) float s_b2[F];
    __shared__ __align__(16) float s_eb1[HID];
    {
        const float4* src;
        float4* dst;
        src = reinterpret_cast<const float4*>(g_nw1t); dst = reinterpret_cast<float4*>(s_w1t);
        for (int i = threadIdx.x; i < (48 * HID) / 4; i += blockDim.x) dst[i] = src[i];
        src = reinterpret_cast<const float4*>(g_nw2t); dst = reinterpret_cast<float4*>(s_w2t);
        for (int i = threadIdx.x; i < (HID * F) / 4; i += blockDim.x) dst[i] = src[i];
        src = reinterpret_cast<const float4*>(g_nws); dst = reinterpret_cast<float4*>(s_ws);
        for (int i = threadIdx.x; i < (16 * HID) / 4; i += blockDim.x) dst[i] = src[i];
        src = reinterpret_cast<const float4*>(g_nwr); dst = reinterpret_cast<float4*>(s_wr);
        for (int i = threadIdx.x; i < (16 * HID) / 4; i += blockDim.x) dst[i] = src[i];
        if (threadIdx.x < HID) { s_b1[threadIdx.x] = g_nb1[threadIdx.x]; s_eb1[threadIdx.x] = g_neb1[threadIdx.x]; }
        if (threadIdx.x < F)   s_b2[threadIdx.x] = g_nb2[threadIdx.x];
    }
    __syncthreads();

    int n = blockIdx.x * blockDim.x + threadIdx.x;
    if (n >= NN) return;

    ull acc[HID / 2];
#pragma unroll
    for (int j = 0; j < HID / 4; j++) {
        ulonglong2 bv = *reinterpret_cast<const ulonglong2*>(&s_b1[j * 4]);
        acc[2 * j] = bv.x; acc[2 * j + 1] = bv.y;
    }
#pragma unroll
    for (int k = 0; k < 16; k++) {
        float xk = src_nodes[(size_t)k * NN + n];
        ull xs = pack2(xk, xk);
        const ulonglong2* w = reinterpret_cast<const ulonglong2*>(&s_w1t[k * HID]);
#pragma unroll
        for (int m = 0; m < 16; m++) {
            ulonglong2 wv = w[m];
            acc[2 * m]     = fma2(wv.x, xs, acc[2 * m]);
            acc[2 * m + 1] = fma2(wv.y, xs, acc[2 * m + 1]);
        }
    }
    const float4 zero4 = make_float4(0.f, 0.f, 0.f, 0.f);
#pragma unroll
    for (int seg = 0; seg < 2; seg++) {
        float* aggr = seg == 0 ? &g_sent[(size_t)n * F] : &g_recv[(size_t)n * F];
        float xv[16];
#pragma unroll
        for (int q = 0; q < 4; q++) {
            float4 v = *reinterpret_cast<const float4*>(&aggr[q * 4]);
            xv[q * 4] = v.x; xv[q * 4 + 1] = v.y; xv[q * 4 + 2] = v.z; xv[q * 4 + 3] = v.w;
            *reinterpret_cast<float4*>(&aggr[q * 4]) = zero4;  // re-zero for next round
        }
#pragma unroll
        for (int k = 0; k < 16; k++) {
            ull xs = pack2(xv[k], xv[k]);
            const ulonglong2* w = reinterpret_cast<const ulonglong2*>(&s_w1t[((seg + 1) * 16 + k) * HID]);
#pragma unroll
            for (int m = 0; m < 16; m++) {
                ulonglong2 wv = w[m];
                acc[2 * m]     = fma2(wv.x, xs, acc[2 * m]);
                acc[2 * m + 1] = fma2(wv.y, xs, acc[2 * m + 1]);
            }
        }
    }

    ull o[F / 2];
#pragma unroll
    for (int j = 0; j < 4; j++) {
        ulonglong2 bv = *reinterpret_cast<const ulonglong2*>(&s_b2[j * 4]);
        o[2 * j] = bv.x; o[2 * j + 1] = bv.y;
    }
#pragma unroll
    for (int h = 0; h < HID; h += 2) {
        float h0, h1; unpack2(acc[h >> 1], h0, h1);
        h0 = fmaxf(h0, 0.f); h1 = fmaxf(h1, 0.f);
        ull x0 = pack2(h0, h0), x1 = pack2(h1, h1);
        const ulonglong2* w0 = reinterpret_cast<const ulonglong2*>(&s_w2t[h * F]);
        const ulonglong2* w1 = reinterpret_cast<const ulonglong2*>(&s_w2t[(h + 1) * F]);
#pragma unroll
        for (int m = 0; m < 4; m++) {
            ulonglong2 a = w0[m], b = w1[m];
            o[2 * m]     = fma2(a.x, x0, o[2 * m]);
            o[2 * m]     = fma2(b.x, x1, o[2 * m]);
            o[2 * m + 1] = fma2(a.y, x0, o[2 * m + 1]);
            o[2 * m + 1] = fma2(b.y, x1, o[2 * m + 1]);
        }
    }
    float y[F];
#pragma unroll
    for (int j = 0; j < F / 2; j++) unpack2(o[j], y[2 * j], y[2 * j + 1]);
#pragma unroll
    for (int k = 0; k < F; k++) {
        g_nodes[(size_t)k * NN + n] = y[k];
    }
    if (out_nodes) {
#pragma unroll
        for (int k = 0; k < F; k++) out_nodes[(size_t)k * NN + n] = y[k];
    }

#pragma unroll
    for (int j = 0; j < HID / 4; j++) {
        ulonglong2 bv = *reinterpret_cast<const ulonglong2*>(&s_eb1[j * 4]);
        acc[2 * j] = bv.x; acc[2 * j + 1] = bv.y;
    }
#pragma unroll
    for (int k = 0; k < 16; k++) {
        ull xs = pack2(y[k], y[k]);
        const ulonglong2* w = reinterpret_cast<const ulonglong2*>(&s_ws[k * HID]);
#pragma unroll
        for (int m = 0; m < 16; m++) {
            ulonglong2 wv = w[m];
            acc[2 * m]     = fma2(wv.x, xs, acc[2 * m]);
            acc[2 * m + 1] = fma2(wv.y, xs, acc[2 * m + 1]);
        }
    }
    ull* outp = reinterpret_cast<ull*>(&g_ps[(size_t)n * HID]);
#pragma unroll
    for (int j = 0; j < HID / 2; j++) outp[j] = acc[j];

#pragma unroll
    for (int j = 0; j < HID / 2; j++) acc[j] = 0ull;
#pragma unroll
    for (int k = 0; k < 16; k++) {
        ull xs = pack2(y[k], y[k]);
        const ulonglong2* w = reinterpret_cast<const ulonglong2*>(&s_wr[k * HID]);
#pragma unroll
        for (int m = 0; m < 16; m++) {
            ulonglong2 wv = w[m];
            acc[2 * m]     = fma2(wv.x, xs, acc[2 * m]);
            acc[2 * m + 1] = fma2(wv.y, xs, acc[2 * m + 1]);
        }
    }
    outp = reinterpret_cast<ull*>(&g_pr[(size_t)n * HID]);
#pragma unroll
    for (int j = 0; j < HID / 2; j++) outp[j] = acc[j];
}

// ---------------- edge MLP v7 (measured best) + cooperative red --------------
#define ETPB 128
#define EPB  128
#define SG_STRIDE 72   // gather row: halves at +0 / +36; also reused as s_out (stride 20)
#define SX_STRIDE 34   // x row per PAIR: [k*2 + half]
#define SO_STRIDE 20   // ov row in reused s_g
#define SG_FLOATS (EPB * SG_STRIDE)
#define SX_FLOATS ((EPB / 2) * SX_STRIDE)
#define EDGE_SMEM_FLOATS (SG_FLOATS + SX_FLOATS + W1_FLOATS + W2_FLOATS + 16)

__global__ void __launch_bounds__(ETPB)
edge_mlp_kernel(const float* src_fe, float* dst_fe,
                const int* __restrict__ snd, const int* __restrict__ rcv,
                int do_scatter) {
    extern __shared__ __align__(16) float smem[];
    float* s_g  = smem;                          // EPB x 72 (split halves); reused as s_out
    float* s_x  = s_g + SG_FLOATS;               // (EPB/2) x 34
    float* s_w1 = s_x + SX_FLOATS;               // 16 x 68 (split halves)
    float* s_w2 = s_w1 + W1_FLOATS;              // 1028 (split at 516)
    float* s_b2 = s_w2 + W2_FLOATS;              // 16

    const int tid  = threadIdx.x;
    const int half = tid & 1;                    // hidden half: h in [32*half, 32*half+32)
    const int pair = tid >> 1;                   // local pair index
    const int e0   = blockIdx.x * EPB;
    const int ee_l = tid & ~1;                   // even local edge of my pair
    const size_t em = (size_t)e0 + tid;          // my OUTPUT edge

    // ---- load my edge's features (coalesced), stage x into smem
    {
        float x[16];
        if (src_fe) {
#pragma unroll
            for (int k = 0; k < 16; k++) x[k] = __ldcs(&src_fe[(size_t)k * EE + em]);
        } else {
#pragma unroll
            for (int q = 0; q < 4; q++) {
                float4 v = __ldcs(reinterpret_cast<const float4*>(&g_edges[em * F + q * 4]));
                x[q * 4] = v.x; x[q * 4 + 1] = v.y; x[q * 4 + 2] = v.z; x[q * 4 + 3] = v.w;
            }
        }
#pragma unroll
        for (int k = 0; k < 16; k++) s_x[pair * SX_STRIDE + 2 * k + half] = x[k];
    }

    // ---- weights: LINEAR float4 loads from pre-transposed globals (L2-hot)
    {
        const float4* w1s = reinterpret_cast<const float4*>(g_w1p);
        float4*       w1d = reinterpret_cast<float4*>(s_w1);
        for (int i = tid; i < W1_FLOATS / 4; i += ETPB) w1d[i] = w1s[i];
        const float4* w2s = reinterpret_cast<const float4*>(g_w2p);
        float4*       w2d = reinterpret_cast<float4*>(s_w2);
        for (int i = tid; i < W2_FLOATS / 4; i += ETPB) w2d[i] = w2s[i];
        if (tid < 16) s_b2[tid] = g_b2p[tid];
    }

    // ---- cooperative gather staging into split rows
    {
        const int wid  = tid >> 5;        // 4 warps, 32 edges each
        const int lane = tid & 31;
        const int sub  = lane >> 4;
        const int c    = lane & 15;
        const int coff = c * 4 + (c >= 8 ? 4 : 0);
#pragma unroll
        for (int i = 0; i < 32; i += 2) {
            int el = wid * 32 + i + sub;
            int s = snd[e0 + el];
            int r = rcv[e0 + el];
            ulonglong2 a = *reinterpret_cast<const ulonglong2*>(&g_ps[(size_t)s * HID + c * 4]);
            ulonglong2 b = *reinterpret_cast<const ulonglong2*>(&g_pr[(size_t)r * HID + c * 4]);
            ulonglong2 v; v.x = add2(a.x, b.x); v.y = add2(a.y, b.y);
            *reinterpret_cast<ulonglong2*>(&s_g[el * SG_STRIDE + coff]) = v;
        }
    }
    __syncthreads();

    // ---- layer-1 accumulators: my half of BOTH edges (eb1 folded in g_ps)
    ull acc0[16], acc1[16];   // acc0: edge ee_l, acc1: edge ee_l+1
    {
        const ulonglong2* g0 = reinterpret_cast<const ulonglong2*>(&s_g[ee_l * SG_STRIDE + half * 36]);
        const ulonglong2* g1 = reinterpret_cast<const ulonglong2*>(&s_g[(ee_l + 1) * SG_STRIDE + half * 36]);
#pragma unroll
        for (int m = 0; m < 8; m++) {
            ulonglong2 v = g0[m]; acc0[2 * m] = v.x; acc0[2 * m + 1] = v.y;
            ulonglong2 u = g1[m]; acc1[2 * m] = u.x; acc1[2 * m + 1] = u.y;
        }
    }

    // ---- layer 1: one LDS.64 per k gives both edges' x; weights shared
#pragma unroll
    for (int k = 0; k < 16; k++) {
        float2 xp = *reinterpret_cast<const float2*>(&s_x[pair * SX_STRIDE + 2 * k]);
        ull xs0 = pack2(xp.x, xp.x);     // edge ee_l
        ull xs1 = pack2(xp.y, xp.y);     // edge ee_l+1
        const ulonglong2* w = reinterpret_cast<const ulonglong2*>(&s_w1[k * 68 + half * 36]);
#pragma unroll
        for (int m = 0; m < 8; m++) {
            ulonglong2 wv = w[m];
            acc0[2 * m]     = fma2(wv.x, xs0, acc0[2 * m]);
            acc0[2 * m + 1] = fma2(wv.y, xs0, acc0[2 * m + 1]);
            acc1[2 * m]     = fma2(wv.x, xs1, acc1[2 * m]);
            acc1[2 * m + 1] = fma2(wv.y, xs1, acc1[2 * m + 1]);
        }
    }

    // ---- layer 2 partials over my 32 h (half 0 carries bias for BOTH edges)
    ull o0[8], o1[8];
    if (half == 0) {
#pragma unroll
        for (int j = 0; j < 4; j++) {
            ulonglong2 bv = *reinterpret_cast<const ulonglong2*>(&s_b2[j * 4]);
            o0[2 * j] = bv.x; o0[2 * j + 1] = bv.y;
            o1[2 * j] = bv.x; o1[2 * j + 1] = bv.y;
        }
    } else {
#pragma unroll
        for (int j = 0; j < 8; j++) { o0[j] = 0ull; o1[j] = 0ull; }
    }
    const float* w2b = s_w2 + (half ? 516 : 0);
#pragma unroll
    for (int it = 0; it < 16; it++) {
        float a0, a1; unpack2(acc0[it], a0, a1);
        a0 = fmaxf(a0, 0.f); a1 = fmaxf(a1, 0.f);
        ull p00 = pack2(a0, a0), p01 = pack2(a1, a1);
        float b0, b1; unpack2(acc1[it], b0, b1);
        b0 = fmaxf(b0, 0.f); b1 = fmaxf(b1, 0.f);
        ull p10 = pack2(b0, b0), p11 = pack2(b1, b1);
        const ulonglong2* w0 = reinterpret_cast<const ulonglong2*>(&w2b[(2 * it) * 16]);
        const ulonglong2* w1 = reinterpret_cast<const ulonglong2*>(&w2b[(2 * it + 1) * 16]);
#pragma unroll
        for (int m = 0; m < 4; m++) {
            ulonglong2 a = w0[m], b = w1[m];
            o0[2 * m]     = fma2(a.x, p00, o0[2 * m]);
            o0[2 * m]     = fma2(b.x, p01, o0[2 * m]);
            o0[2 * m + 1] = fma2(a.y, p00, o0[2 * m + 1]);
            o0[2 * m + 1] = fma2(b.y, p01, o0[2 * m + 1]);
            o1[2 * m]     = fma2(a.x, p10, o1[2 * m]);
            o1[2 * m]     = fma2(b.x, p11, o1[2 * m]);
            o1[2 * m + 1] = fma2(a.y, p10, o1[2 * m + 1]);
            o1[2 * m + 1] = fma2(b.y, p11, o1[2 * m + 1]);
        }
    }

    // ---- single exchange: send partner's-edge partial, receive mine
    float ov[16];
#pragma unroll
    for (int j = 0; j < 8; j++) {
        ull sel  = half ? o0[j] : o1[j];            // partial for PARTNER's edge
        ull rec  = __shfl_xor_sync(0xFFFFFFFFu, sel, 1);
        ull mine = half ? o1[j] : o0[j];            // my partial for MY edge
        ull tot  = add2(mine, rec);
        unpack2(tot, ov[2 * j], ov[2 * j + 1]);
    }

    // ---- write my edge's new features
    if (dst_fe) {
#pragma unroll
        for (int f = 0; f < F; f++) __stcs(&dst_fe[(size_t)f * EE + em], ov[f]);
    } else {
#pragma unroll
        for (int q = 0; q < 4; q++) {
            float4 v = make_float4(ov[q * 4], ov[q * 4 + 1], ov[q * 4 + 2], ov[q * 4 + 3]);
            __stcs(reinterpret_cast<float4*>(&g_edges[em * F + q * 4]), v);
        }
    }

    // ---- cooperative red phase: 4 lanes cover one edge's 64B row -> 1 line
    if (do_scatter) {
        float* s_out = s_g;                       // staging buffer is dead; reuse
        __syncthreads();
#pragma unroll
        for (int q = 0; q < 4; q++) {
            float4 v = make_float4(ov[q * 4], ov[q * 4 + 1], ov[q * 4 + 2], ov[q * 4 + 3]);
            *reinterpret_cast<float4*>(&s_out[tid * SO_STRIDE + q * 4]) = v;
        }
        __syncthreads();
#pragma unroll
        for (int p = 0; p < 8; p++) {
            int g = tid + p * ETPB;
            int chunk = g & 3;
            int which = (g >> 2) & 1;
            int el    = g >> 3;
            int node  = which ? rcv[e0 + el] : snd[e0 + el];
            float* base = which ? g_recv : g_sent;
            float4 v = *reinterpret_cast<const float4*>(&s_out[el * SO_STRIDE + chunk * 4]);
            asm volatile("red.global.add.v4.f32 [%0], {%1,%2,%3,%4};"
                         :: "l"(base + (size_t)node * F + chunk * 4),
                            "f"(v.x), "f"(v.y), "f"(v.z), "f"(v.w)
                         : "memory");
        }
    }
}

extern "C" void kernel_launch(void* const* d_in, const int* in_sizes, int n_in,
                              void* d_out, int out_size) {
    const float* nodes     = (const float*)d_in[0];
    const float* edges     = (const float*)d_in[1];
    const int*   receivers = (const int*)  d_in[2];
    const int*   senders   = (const int*)  d_in[3];
    const float* nW1 = (const float*)d_in[4];
    const float* nb1 = (const float*)d_in[5];
    const float* nW2 = (const float*)d_in[6];
    const float* nb2 = (const float*)d_in[7];
    const float* eW1 = (const float*)d_in[8];
    const float* eb1 = (const float*)d_in[9];
    const float* eW2 = (const float*)d_in[10];
    const float* eb2 = (const float*)d_in[11];
    float* out_nodes = (float*)d_out;
    float* out_edges = (float*)d_out + (size_t)F * NN;

    const int EDGE_BLOCKS = EE / EPB;                  // 25000
    const int NODE_BLOCKS = (NN + 255) / 256;          // 391
    const int ZERO_BLOCKS = ((NN * F) / 4 + 255) / 256;
    const int EDGE_SMEM = EDGE_SMEM_FLOATS * 4;        // ~54.1 KB

    static int configured = 0;
    if (!configured) {
        cudaFuncSetAttribute(edge_mlp_kernel, cudaFuncAttributeMaxDynamicSharedMemorySize, EDGE_SMEM);
        configured = 1;
    }

    prep_weights_kernel<<<1, 256>>>(eW1, eW2, eb2, nW1, nb1, nW2, nb2, eb1);
    zero_agg_kernel<<<ZERO_BLOCKS, 256>>>();
    scatter_kernel<<<EE / STPB, STPB>>>(edges, senders, receivers);

    for (int round = 0; round < ROUNDS; round++) {
        node_proj_kernel<<<NODE_BLOCKS, 256>>>(
            (round == 0) ? nodes : (const float*)0,
            (round == ROUNDS - 1) ? out_nodes : (float*)0);
        edge_mlp_kernel<<<EDGE_BLOCKS, ETPB, EDGE_SMEM>>>(
            (round == 0) ? edges : (const float*)0,
            (round == ROUNDS - 1) ? out_edges : (float*)0,
            senders, receivers, (round < ROUNDS - 1) ? 1 : 0);
    }
}

// round 13
// speedup vs baseline: 1.1437x; 1.0241x over previous
#include <cuda_runtime.h>

#define F   16
#define HID 64
#define NN  100000
#define EE  3200000
#define ROUNDS 5

typedef unsigned long long ull;

__device__ __align__(256) float g_edges[(size_t)EE * F];   // [E][F] internal layout
__device__ __align__(256) float g_nodes[F * NN];           // [F][N]
__device__ __align__(256) float g_sent[NN * F];            // [N][F]
__device__ __align__(256) float g_recv[NN * F];            // [N][F]
__device__ __align__(256) float g_ps[NN * HID];            // [N][HID]  eW1_s @ nodes + eb1
__device__ __align__(256) float g_pr[NN * HID];            // [N][HID]  eW1_r @ nodes

// pre-transposed edge-MLP weights, HALF-INTERLEAVED so pair-lanes hit one line:
//   w1: [k][m][half][4]  -> offset k*64 + m*8 + half*4          (1024 floats)
//   w2: [hh][m][half][4] -> offset hh*32 + m*8 + half*4          (1024 floats)
#define W1_FLOATS 1024
#define W2_FLOATS 1024
__device__ __align__(256) float g_w1p[W1_FLOATS];
__device__ __align__(256) float g_w2p[W2_FLOATS];
__device__ __align__(256) float g_b2p[16];

// pre-transposed node-MLP + projection weights
__device__ __align__(256) float g_nw1t[48 * HID];   // [k][h]
__device__ __align__(256) float g_nw2t[HID * F];    // [h][o]
__device__ __align__(256) float g_nws[16 * HID];    // eW1 cols 16..31, [k][h]
__device__ __align__(256) float g_nwr[16 * HID];    // eW1 cols 32..47, [k][h]
__device__ __align__(256) float g_nb1[HID];
__device__ __align__(256) float g_nb2[F];
__device__ __align__(256) float g_neb1[HID];

__device__ __forceinline__ ull pack2(float a, float b) {
    ull r; asm("mov.b64 %0, {%1,%2};" : "=l"(r) : "f"(a), "f"(b)); return r;
}
__device__ __forceinline__ void unpack2(ull v, float& a, float& b) {
    asm("mov.b64 {%0,%1}, %2;" : "=f"(a), "=f"(b) : "l"(v));
}
__device__ __forceinline__ ull fma2(ull a, ull b, ull c) {
    ull d; asm("fma.rn.f32x2 %0, %1, %2, %3;" : "=l"(d) : "l"(a), "l"(b), "l"(c)); return d;
}
__device__ __forceinline__ ull add2(ull a, ull b) {
    ull d; asm("add.rn.f32x2 %0, %1, %2;" : "=l"(d) : "l"(a), "l"(b)); return d;
}

// one-time: transpose ALL weights into kernel-friendly layouts
__global__ void prep_weights_kernel(const float* __restrict__ eW1,
                                    const float* __restrict__ eW2,
                                    const float* __restrict__ eb2,
                                    const float* __restrict__ nW1,
                                    const float* __restrict__ nb1,
                                    const float* __restrict__ nW2,
                                    const float* __restrict__ nb2,
                                    const float* __restrict__ eb1) {
    int tid = threadIdx.x;
    for (int i = tid; i < 16 * 64; i += blockDim.x) {
        int k = i >> 6, h = i & 63;
        int half = (h >= 32) ? 1 : 0;
        int hh = h & 31;
        int m = hh >> 2, j = hh & 3;
        g_w1p[k * 64 + m * 8 + half * 4 + j] = eW1[h * 48 + k];   // half-interleaved
        g_nws[k * HID + h] = eW1[h * 48 + 16 + k];
        g_nwr[k * HID + h] = eW1[h * 48 + 32 + k];
    }
    for (int i = tid; i < 64 * 16; i += blockDim.x) {
        int h = i >> 4, o = i & 15;
        int half = (h >= 32) ? 1 : 0;
        int hh = h - 32 * half;
        g_w2p[hh * 32 + (o >> 2) * 8 + half * 4 + (o & 3)] = eW2[o * 64 + h];  // half-interleaved
        g_nw2t[h * F + o] = nW2[o * HID + h];
    }
    for (int i = tid; i < 48 * 64; i += blockDim.x) {
        int k = i >> 6, h = i & 63;
        g_nw1t[k * HID + h] = nW1[h * 48 + k];
    }
    if (tid < 16) { g_b2p[tid] = eb2[tid]; g_nb2[tid] = nb2[tid]; }
    if (tid < HID) { g_nb1[tid] = nb1[tid]; g_neb1[tid] = eb1[tid]; }
}

__global__ void zero_agg_kernel() {
    int i = blockIdx.x * blockDim.x + threadIdx.x;
    const int n4 = (NN * F) / 4;
    float4 z = make_float4(0.f, 0.f, 0.f, 0.f);
    if (i < n4) {
        reinterpret_cast<float4*>(g_sent)[i] = z;
        reinterpret_cast<float4*>(g_recv)[i] = z;
    }
}

// round-0 scatter (cooperative red): reads the ORIGINAL [F][E] input edges
#define STPB 256
#define SV_STRIDE 20
__global__ void __launch_bounds__(STPB)
scatter_kernel(const float* __restrict__ edges,
               const int* __restrict__ snd, const int* __restrict__ rcv) {
    __shared__ __align__(16) float s_v[STPB * SV_STRIDE];
    const int tid = threadIdx.x;
    const int e0 = blockIdx.x * STPB;
    const size_t e = (size_t)e0 + tid;

    float v[F];
#pragma unroll
    for (int f = 0; f < F; f++) v[f] = __ldcs(&edges[(size_t)f * EE + e]);
#pragma unroll
    for (int q = 0; q < 4; q++) {
        float4 w = make_float4(v[q * 4], v[q * 4 + 1], v[q * 4 + 2], v[q * 4 + 3]);
        *reinterpret_cast<float4*>(&s_v[tid * SV_STRIDE + q * 4]) = w;
    }
    __syncthreads();
#pragma unroll
    for (int p = 0; p < 8; p++) {
        int g = tid + p * STPB;
        int chunk = g & 3;
        int which = (g >> 2) & 1;
        int el    = g >> 3;
        int node  = which ? rcv[e0 + el] : snd[e0 + el];
        float* base = which ? g_recv : g_sent;
        float4 w = *reinterpret_cast<const float4*>(&s_v[el * SV_STRIDE + chunk * 4]);
        asm volatile("red.global.add.v4.f32 [%0], {%1,%2,%3,%4};"
                     :: "l"(base + (size_t)node * F + chunk * 4),
                        "f"(w.x), "f"(w.y), "f"(w.z), "f"(w.w)
                     : "memory");
    }
}

// fused node MLP + edge projections + aggregate re-zeroing (prepped weights)
__global__ void __launch_bounds__(256)
node_proj_kernel(const float* src_nodes_in, float* out_nodes) {
    const float* __restrict__ src_nodes = src_nodes_in ? src_nodes_in : g_nodes;
    __shared__ __align__(16) float s_w1t[48 * HID];
    __shared__ __align__(16) float s_w2t[HID * F];
    __shared__ __align__(16) float s_ws[16 * HID];
    __shared__ __align__(16) float s_wr[16 * HID];
    __shared__ __align__(16) float s_b1[HID];
    __shared__ __align__(16) float s_b2[F];
    __shared__ __align__(16) float s_eb1[HID];
    {
        const float4* src;
        float4* dst;
        src = reinterpret_cast<const float4*>(g_nw1t); dst = reinterpret_cast<float4*>(s_w1t);
        for (int i = threadIdx.x; i < (48 * HID) / 4; i += blockDim.x) dst[i] = src[i];
        src = reinterpret_cast<const float4*>(g_nw2t); dst = reinterpret_cast<float4*>(s_w2t);
        for (int i = threadIdx.x; i < (HID * F) / 4; i += blockDim.x) dst[i] = src[i];
        src = reinterpret_cast<const float4*>(g_nws); dst = reinterpret_cast<float4*>(s_ws);
        for (int i = threadIdx.x; i < (16 * HID) / 4; i += blockDim.x) dst[i] = src[i];
        src = reinterpret_cast<const float4*>(g_nwr); dst = reinterpret_cast<float4*>(s_wr);
        for (int i = threadIdx.x; i < (16 * HID) / 4; i += blockDim.x) dst[i] = src[i];
        if (threadIdx.x < HID) { s_b1[threadIdx.x] = g_nb1[threadIdx.x]; s_eb1[threadIdx.x] = g_neb1[threadIdx.x]; }
        if (threadIdx.x < F)   s_b2[threadIdx.x] = g_nb2[threadIdx.x];
    }
    __syncthreads();

    int n = blockIdx.x * blockDim.x + threadIdx.x;
    if (n >= NN) return;

    ull acc[HID / 2];
#pragma unroll
    for (int j = 0; j < HID / 4; j++) {
        ulonglong2 bv = *reinterpret_cast<const ulonglong2*>(&s_b1[j * 4]);
        acc[2 * j] = bv.x; acc[2 * j + 1] = bv.y;
    }
#pragma unroll
    for (int k = 0; k < 16; k++) {
        float xk = src_nodes[(size_t)k * NN + n];
        ull xs = pack2(xk, xk);
        const ulonglong2* w = reinterpret_cast<const ulonglong2*>(&s_w1t[k * HID]);
#pragma unroll
        for (int m = 0; m < 16; m++) {
            ulonglong2 wv = w[m];
            acc[2 * m]     = fma2(wv.x, xs, acc[2 * m]);
            acc[2 * m + 1] = fma2(wv.y, xs, acc[2 * m + 1]);
        }
    }
    const float4 zero4 = make_float4(0.f, 0.f, 0.f, 0.f);
#pragma unroll
    for (int seg = 0; seg < 2; seg++) {
        float* aggr = seg == 0 ? &g_sent[(size_t)n * F] : &g_recv[(size_t)n * F];
        float xv[16];
#pragma unroll
        for (int q = 0; q < 4; q++) {
            float4 v = *reinterpret_cast<const float4*>(&aggr[q * 4]);
            xv[q * 4] = v.x; xv[q * 4 + 1] = v.y; xv[q * 4 + 2] = v.z; xv[q * 4 + 3] = v.w;
            *reinterpret_cast<float4*>(&aggr[q * 4]) = zero4;  // re-zero for next round
        }
#pragma unroll
        for (int k = 0; k < 16; k++) {
            ull xs = pack2(xv[k], xv[k]);
            const ulonglong2* w = reinterpret_cast<const ulonglong2*>(&s_w1t[((seg + 1) * 16 + k) * HID]);
#pragma unroll
            for (int m = 0; m < 16; m++) {
                ulonglong2 wv = w[m];
                acc[2 * m]     = fma2(wv.x, xs, acc[2 * m]);
                acc[2 * m + 1] = fma2(wv.y, xs, acc[2 * m + 1]);
            }
        }
    }

    ull o[F / 2];
#pragma unroll
    for (int j = 0; j < 4; j++) {
        ulonglong2 bv = *reinterpret_cast<const ulonglong2*>(&s_b2[j * 4]);
        o[2 * j] = bv.x; o[2 * j + 1] = bv.y;
    }
#pragma unroll
    for (int h = 0; h < HID; h += 2) {
        float h0, h1; unpack2(acc[h >> 1], h0, h1);
        h0 = fmaxf(h0, 0.f); h1 = fmaxf(h1, 0.f);
        ull x0 = pack2(h0, h0), x1 = pack2(h1, h1);
        const ulonglong2* w0 = reinterpret_cast<const ulonglong2*>(&s_w2t[h * F]);
        const ulonglong2* w1 = reinterpret_cast<const ulonglong2*>(&s_w2t[(h + 1) * F]);
#pragma unroll
        for (int m = 0; m < 4; m++) {
            ulonglong2 a = w0[m], b = w1[m];
            o[2 * m]     = fma2(a.x, x0, o[2 * m]);
            o[2 * m]     = fma2(b.x, x1, o[2 * m]);
            o[2 * m + 1] = fma2(a.y, x0, o[2 * m + 1]);
            o[2 * m + 1] = fma2(b.y, x1, o[2 * m + 1]);
        }
    }
    float y[F];
#pragma unroll
    for (int j = 0; j < F / 2; j++) unpack2(o[j], y[2 * j], y[2 * j + 1]);
#pragma unroll
    for (int k = 0; k < F; k++) {
        g_nodes[(size_t)k * NN + n] = y[k];
    }
    if (out_nodes) {
#pragma unroll
        for (int k = 0; k < F; k++) out_nodes[(size_t)k * NN + n] = y[k];
    }

#pragma unroll
    for (int j = 0; j < HID / 4; j++) {
        ulonglong2 bv = *reinterpret_cast<const ulonglong2*>(&s_eb1[j * 4]);
        acc[2 * j] = bv.x; acc[2 * j + 1] = bv.y;
    }
#pragma unroll
    for (int k = 0; k < 16; k++) {
        ull xs = pack2(y[k], y[k]);
        const ulonglong2* w = reinterpret_cast<const ulonglong2*>(&s_ws[k * HID]);
#pragma unroll
        for (int m = 0; m < 16; m++) {
            ulonglong2 wv = w[m];
            acc[2 * m]     = fma2(wv.x, xs, acc[2 * m]);
            acc[2 * m + 1] = fma2(wv.y, xs, acc[2 * m + 1]);
        }
    }
    ull* outp = reinterpret_cast<ull*>(&g_ps[(size_t)n * HID]);
#pragma unroll
    for (int j = 0; j < HID / 2; j++) outp[j] = acc[j];

#pragma unroll
    for (int j = 0; j < HID / 2; j++) acc[j] = 0ull;
#pragma unroll
    for (int k = 0; k < 16; k++) {
        ull xs = pack2(y[k], y[k]);
        const ulonglong2* w = reinterpret_cast<const ulonglong2*>(&s_wr[k * HID]);
#pragma unroll
        for (int m = 0; m < 16; m++) {
            ulonglong2 wv = w[m];
            acc[2 * m]     = fma2(wv.x, xs, acc[2 * m]);
            acc[2 * m + 1] = fma2(wv.y, xs, acc[2 * m + 1]);
        }
    }
    outp = reinterpret_cast<ull*>(&g_pr[(size_t)n * HID]);
#pragma unroll
    for (int j = 0; j < HID / 2; j++) outp[j] = acc[j];
}

// ---------------- edge MLP v9: v7 + half-interleaved weights (1 wf/LDS) ------
#define ETPB 128
#define EPB  128
#define SG_STRIDE 72   // gather row: halves at +0 / +36; also reused as s_out (stride 20)
#define SX_STRIDE 34   // x row per PAIR: [k*2 + half]
#define SO_STRIDE 20   // ov row in reused s_g
#define SG_FLOATS (EPB * SG_STRIDE)
#define SX_FLOATS ((EPB / 2) * SX_STRIDE)
#define EDGE_SMEM_FLOATS (SG_FLOATS + SX_FLOATS + W1_FLOATS + W2_FLOATS + 16)

__global__ void __launch_bounds__(ETPB)
edge_mlp_kernel(const float* src_fe, float* dst_fe,
                const int* __restrict__ snd, const int* __restrict__ rcv,
                int do_scatter) {
    extern __shared__ __align__(16) float smem[];
    float* s_g  = smem;                          // EPB x 72 (split halves); reused as s_out
    float* s_x  = s_g + SG_FLOATS;               // (EPB/2) x 34
    float* s_w1 = s_x + SX_FLOATS;               // 1024, half-interleaved
    float* s_w2 = s_w1 + W1_FLOATS;              // 1024, half-interleaved
    float* s_b2 = s_w2 + W2_FLOATS;              // 16

    const int tid  = threadIdx.x;
    const int half = tid & 1;                    // hidden half: h in [32*half, 32*half+32)
    const int pair = tid >> 1;                   // local pair index
    const int e0   = blockIdx.x * EPB;
    const int ee_l = tid & ~1;                   // even local edge of my pair
    const size_t em = (size_t)e0 + tid;          // my OUTPUT edge

    // ---- load my edge's features (coalesced), stage x into smem
    {
        float x[16];
        if (src_fe) {
#pragma unroll
            for (int k = 0; k < 16; k++) x[k] = __ldcs(&src_fe[(size_t)k * EE + em]);
        } else {
#pragma unroll
            for (int q = 0; q < 4; q++) {
                float4 v = __ldcs(reinterpret_cast<const float4*>(&g_edges[em * F + q * 4]));
                x[q * 4] = v.x; x[q * 4 + 1] = v.y; x[q * 4 + 2] = v.z; x[q * 4 + 3] = v.w;
            }
        }
#pragma unroll
        for (int k = 0; k < 16; k++) s_x[pair * SX_STRIDE + 2 * k + half] = x[k];
    }

    // ---- weights: LINEAR float4 loads from pre-transposed globals (L2-hot)
    {
        const float4* w1s = reinterpret_cast<const float4*>(g_w1p);
        float4*       w1d = reinterpret_cast<float4*>(s_w1);
        for (int i = tid; i < W1_FLOATS / 4; i += ETPB) w1d[i] = w1s[i];
        const float4* w2s = reinterpret_cast<const float4*>(g_w2p);
        float4*       w2d = reinterpret_cast<float4*>(s_w2);
        for (int i = tid; i < W2_FLOATS / 4; i += ETPB) w2d[i] = w2s[i];
        if (tid < 16) s_b2[tid] = g_b2p[tid];
    }

    // ---- cooperative gather staging into split rows
    {
        const int wid  = tid >> 5;        // 4 warps, 32 edges each
        const int lane = tid & 31;
        const int sub  = lane >> 4;
        const int c    = lane & 15;
        const int coff = c * 4 + (c >= 8 ? 4 : 0);
#pragma unroll
        for (int i = 0; i < 32; i += 2) {
            int el = wid * 32 + i + sub;
            int s = snd[e0 + el];
            int r = rcv[e0 + el];
            ulonglong2 a = *reinterpret_cast<const ulonglong2*>(&g_ps[(size_t)s * HID + c * 4]);
            ulonglong2 b = *reinterpret_cast<const ulonglong2*>(&g_pr[(size_t)r * HID + c * 4]);
            ulonglong2 v; v.x = add2(a.x, b.x); v.y = add2(a.y, b.y);
            *reinterpret_cast<ulonglong2*>(&s_g[el * SG_STRIDE + coff]) = v;
        }
    }
    __syncthreads();

    // ---- layer-1 accumulators: my half of BOTH edges (eb1 folded in g_ps)
    ull acc0[16], acc1[16];   // acc0: edge ee_l, acc1: edge ee_l+1
    {
        const ulonglong2* g0 = reinterpret_cast<const ulonglong2*>(&s_g[ee_l * SG_STRIDE + half * 36]);
        const ulonglong2* g1 = reinterpret_cast<const ulonglong2*>(&s_g[(ee_l + 1) * SG_STRIDE + half * 36]);
#pragma unroll
        for (int m = 0; m < 8; m++) {
            ulonglong2 v = g0[m]; acc0[2 * m] = v.x; acc0[2 * m + 1] = v.y;
            ulonglong2 u = g1[m]; acc1[2 * m] = u.x; acc1[2 * m + 1] = u.y;
        }
    }

    // ---- layer 1: one LDS.64 per k gives both edges' x; weights half-interleaved
#pragma unroll
    for (int k = 0; k < 16; k++) {
        float2 xp = *reinterpret_cast<const float2*>(&s_x[pair * SX_STRIDE + 2 * k]);
        ull xs0 = pack2(xp.x, xp.x);     // edge ee_l
        ull xs1 = pack2(xp.y, xp.y);     // edge ee_l+1
#pragma unroll
        for (int m = 0; m < 8; m++) {
            ulonglong2 wv = *reinterpret_cast<const ulonglong2*>(&s_w1[k * 64 + m * 8 + half * 4]);
            acc0[2 * m]     = fma2(wv.x, xs0, acc0[2 * m]);
            acc0[2 * m + 1] = fma2(wv.y, xs0, acc0[2 * m + 1]);
            acc1[2 * m]     = fma2(wv.x, xs1, acc1[2 * m]);
            acc1[2 * m + 1] = fma2(wv.y, xs1, acc1[2 * m + 1]);
        }
    }

    // ---- layer 2 partials over my 32 h (half 0 carries bias for BOTH edges)
    ull o0[8], o1[8];
    if (half == 0) {
#pragma unroll
        for (int j = 0; j < 4; j++) {
            ulonglong2 bv = *reinterpret_cast<const ulonglong2*>(&s_b2[j * 4]);
            o0[2 * j] = bv.x; o0[2 * j + 1] = bv.y;
            o1[2 * j] = bv.x; o1[2 * j + 1] = bv.y;
        }
    } else {
#pragma unroll
        for (int j = 0; j < 8; j++) { o0[j] = 0ull; o1[j] = 0ull; }
    }
#pragma unroll
    for (int it = 0; it < 16; it++) {
        float a0, a1; unpack2(acc0[it], a0, a1);
        a0 = fmaxf(a0, 0.f); a1 = fmaxf(a1, 0.f);
        ull p00 = pack2(a0, a0), p01 = pack2(a1, a1);
        float b0, b1; unpack2(acc1[it], b0, b1);
        b0 = fmaxf(b0, 0.f); b1 = fmaxf(b1, 0.f);
        ull p10 = pack2(b0, b0), p11 = pack2(b1, b1);
#pragma unroll
        for (int m = 0; m < 4; m++) {
            ulonglong2 a = *reinterpret_cast<const ulonglong2*>(&s_w2[(2 * it) * 32 + m * 8 + half * 4]);
            ulonglong2 b = *reinterpret_cast<const ulonglong2*>(&s_w2[(2 * it + 1) * 32 + m * 8 + half * 4]);
            o0[2 * m]     = fma2(a.x, p00, o0[2 * m]);
            o0[2 * m]     = fma2(b.x, p01, o0[2 * m]);
            o0[2 * m + 1] = fma2(a.y, p00, o0[2 * m + 1]);
            o0[2 * m + 1] = fma2(b.y, p01, o0[2 * m + 1]);
            o1[2 * m]     = fma2(a.x, p10, o1[2 * m]);
            o1[2 * m]     = fma2(b.x, p11, o1[2 * m]);
            o1[2 * m + 1] = fma2(a.y, p10, o1[2 * m + 1]);
            o1[2 * m + 1] = fma2(b.y, p11, o1[2 * m + 1]);
        }
    }

    // ---- single exchange: send partner's-edge partial, receive mine
    float ov[16];
#pragma unroll
    for (int j = 0; j < 8; j++) {
        ull sel  = half ? o0[j] : o1[j];            // partial for PARTNER's edge
        ull rec  = __shfl_xor_sync(0xFFFFFFFFu, sel, 1);
        ull mine = half ? o1[j] : o0[j];            // my partial for MY edge
        ull tot  = add2(mine, rec);
        unpack2(tot, ov[2 * j], ov[2 * j + 1]);
    }

    // ---- write my edge's new features
    if (dst_fe) {
#pragma unroll
        for (int f = 0; f < F; f++) __stcs(&dst_fe[(size_t)f * EE + em], ov[f]);
    } else {
#pragma unroll
        for (int q = 0; q < 4; q++) {
            float4 v = make_float4(ov[q * 4], ov[q * 4 + 1], ov[q * 4 + 2], ov[q * 4 + 3]);
            __stcs(reinterpret_cast<float4*>(&g_edges[em * F + q * 4]), v);
        }
    }

    // ---- cooperative red phase: 4 lanes cover one edge's 64B row -> 1 line
    if (do_scatter) {
        float* s_out = s_g;                       // staging buffer is dead; reuse
        __syncthreads();
#pragma unroll
        for (int q = 0; q < 4; q++) {
            float4 v = make_float4(ov[q * 4], ov[q * 4 + 1], ov[q * 4 + 2], ov[q * 4 + 3]);
            *reinterpret_cast<float4*>(&s_out[tid * SO_STRIDE + q * 4]) = v;
        }
        __syncthreads();
#pragma unroll
        for (int p = 0; p < 8; p++) {
            int g = tid + p * ETPB;
            int chunk = g & 3;
            int which = (g >> 2) & 1;
            int el    = g >> 3;
            int node  = which ? rcv[e0 + el] : snd[e0 + el];
            float* base = which ? g_recv : g_sent;
            float4 v = *reinterpret_cast<const float4*>(&s_out[el * SO_STRIDE + chunk * 4]);
            asm volatile("red.global.add.v4.f32 [%0], {%1,%2,%3,%4};"
                         :: "l"(base + (size_t)node * F + chunk * 4),
                            "f"(v.x), "f"(v.y), "f"(v.z), "f"(v.w)
                         : "memory");
        }
    }
}

extern "C" void kernel_launch(void* const* d_in, const int* in_sizes, int n_in,
                              void* d_out, int out_size) {
    const float* nodes     = (const float*)d_in[0];
    const float* edges     = (const float*)d_in[1];
    const int*   receivers = (const int*)  d_in[2];
    const int*   senders   = (const int*)  d_in[3];
    const float* nW1 = (const float*)d_in[4];
    const float* nb1 = (const float*)d_in[5];
    const float* nW2 = (const float*)d_in[6];
    const float* nb2 = (const float*)d_in[7];
    const float* eW1 = (const float*)d_in[8];
    const float* eb1 = (const float*)d_in[9];
    const float* eW2 = (const float*)d_in[10];
    const float* eb2 = (const float*)d_in[11];
    float* out_nodes = (float*)d_out;
    float* out_edges = (float*)d_out + (size_t)F * NN;

    const int EDGE_BLOCKS = EE / EPB;                  // 25000
    const int NODE_BLOCKS = (NN + 255) / 256;          // 391
    const int ZERO_BLOCKS = ((NN * F) / 4 + 255) / 256;
    const int EDGE_SMEM = EDGE_SMEM_FLOATS * 4;        // ~53.8 KB

    static int configured = 0;
    if (!configured) {
        cudaFuncSetAttribute(edge_mlp_kernel, cudaFuncAttributeMaxDynamicSharedMemorySize, EDGE_SMEM);
        configured = 1;
    }

    prep_weights_kernel<<<1, 256>>>(eW1, eW2, eb2, nW1, nb1, nW2, nb2, eb1);
    zero_agg_kernel<<<ZERO_BLOCKS, 256>>>();
    scatter_kernel<<<EE / STPB, STPB>>>(edges, senders, receivers);

    for (int round = 0; round < ROUNDS; round++) {
        node_proj_kernel<<<NODE_BLOCKS, 256>>>(
            (round == 0) ? nodes : (const float*)0,
            (round == ROUNDS - 1) ? out_nodes : (float*)0);
        edge_mlp_kernel<<<EDGE_BLOCKS, ETPB, EDGE_SMEM>>>(
            (round == 0) ? edges : (const float*)0,
            (round == ROUNDS - 1) ? out_edges : (float*)0,
            senders, receivers, (round < ROUNDS - 1) ? 1 : 0);
    }
}

// round 16
// speedup vs baseline: 1.2545x; 1.0969x over previous
#include <cuda_runtime.h>
#include <cuda_fp16.h>

#define F   16
#define HID 64
#define NN  100000
#define EE  3200000
#define ROUNDS 5

// fp16 projection tables are stored scaled by 2^-8 (exact exponent shift) to
// avoid overflow as magnitudes grow across rounds; rescaled by 2^8 on gather.
#define P_SCALE_DOWN 0.00390625f   // 2^-8
#define P_SCALE_UP   256.0f        // 2^8

typedef unsigned long long ull;

__device__ __align__(256) float g_edges[(size_t)EE * F];   // [E][F] internal layout
__device__ __align__(256) float g_nodes[F * NN];           // [F][N]
__device__ __align__(256) float g_sent[NN * F];            // [N][F]
__device__ __align__(256) float g_recv[NN * F];            // [N][F]
__device__ __align__(256) __half g_ps[NN * HID];           // fp16 [N][HID] (eW1_s@nodes+eb1)*2^-8
__device__ __align__(256) __half g_pr[NN * HID];           // fp16 [N][HID] (eW1_r@nodes)*2^-8

// pre-transposed edge-MLP weights, HALF-INTERLEAVED so pair-lanes hit one line:
//   w1: [k][m][half][4]  -> offset k*64 + m*8 + half*4          (1024 floats)
//   w2: [hh][m][half][4] -> offset hh*32 + m*8 + half*4          (1024 floats)
#define W1_FLOATS 1024
#define W2_FLOATS 1024
__device__ __align__(256) float g_w1p[W1_FLOATS];
__device__ __align__(256) float g_w2p[W2_FLOATS];
__device__ __align__(256) float g_b2p[16];

// pre-transposed node-MLP + projection weights
__device__ __align__(256) float g_nw1t[48 * HID];   // [k][h]
__device__ __align__(256) float g_nw2t[HID * F];    // [h][o]
__device__ __align__(256) float g_nws[16 * HID];    // eW1 cols 16..31, [k][h]
__device__ __align__(256) float g_nwr[16 * HID];    // eW1 cols 32..47, [k][h]
__device__ __align__(256) float g_nb1[HID];
__device__ __align__(256) float g_nb2[F];
__device__ __align__(256) float g_neb1[HID];

__device__ __forceinline__ ull pack2(float a, float b) {
    ull r; asm("mov.b64 %0, {%1,%2};" : "=l"(r) : "f"(a), "f"(b)); return r;
}
__device__ __forceinline__ void unpack2(ull v, float& a, float& b) {
    asm("mov.b64 {%0,%1}, %2;" : "=f"(a), "=f"(b) : "l"(v));
}
__device__ __forceinline__ ull fma2(ull a, ull b, ull c) {
    ull d; asm("fma.rn.f32x2 %0, %1, %2, %3;" : "=l"(d) : "l"(a), "l"(b), "l"(c)); return d;
}
__device__ __forceinline__ ull add2(ull a, ull b) {
    ull d; asm("add.rn.f32x2 %0, %1, %2;" : "=l"(d) : "l"(a), "l"(b)); return d;
}

// one-time: transpose ALL weights into kernel-friendly layouts
__global__ void prep_weights_kernel(const float* __restrict__ eW1,
                                    const float* __restrict__ eW2,
                                    const float* __restrict__ eb2,
                                    const float* __restrict__ nW1,
                                    const float* __restrict__ nb1,
                                    const float* __restrict__ nW2,
                                    const float* __restrict__ nb2,
                                    const float* __restrict__ eb1) {
    int tid = threadIdx.x;
    for (int i = tid; i < 16 * 64; i += blockDim.x) {
        int k = i >> 6, h = i & 63;
        int half = (h >= 32) ? 1 : 0;
        int hh = h & 31;
        int m = hh >> 2, j = hh & 3;
        g_w1p[k * 64 + m * 8 + half * 4 + j] = eW1[h * 48 + k];   // half-interleaved
        g_nws[k * HID + h] = eW1[h * 48 + 16 + k];
        g_nwr[k * HID + h] = eW1[h * 48 + 32 + k];
    }
    for (int i = tid; i < 64 * 16; i += blockDim.x) {
        int h = i >> 4, o = i & 15;
        int half = (h >= 32) ? 1 : 0;
        int hh = h - 32 * half;
        g_w2p[hh * 32 + (o >> 2) * 8 + half * 4 + (o & 3)] = eW2[o * 64 + h];  // half-interleaved
        g_nw2t[h * F + o] = nW2[o * HID + h];
    }
    for (int i = tid; i < 48 * 64; i += blockDim.x) {
        int k = i >> 6, h = i & 63;
        g_nw1t[k * HID + h] = nW1[h * 48 + k];
    }
    if (tid < 16) { g_b2p[tid] = eb2[tid]; g_nb2[tid] = nb2[tid]; }
    if (tid < HID) { g_nb1[tid] = nb1[tid]; g_neb1[tid] = eb1[tid]; }
}

__global__ void zero_agg_kernel() {
    int i = blockIdx.x * blockDim.x + threadIdx.x;
    const int n4 = (NN * F) / 4;
    float4 z = make_float4(0.f, 0.f, 0.f, 0.f);
    if (i < n4) {
        reinterpret_cast<float4*>(g_sent)[i] = z;
        reinterpret_cast<float4*>(g_recv)[i] = z;
    }
}

// round-0 scatter (cooperative red): reads the ORIGINAL [F][E] input edges
#define STPB 256
#define SV_STRIDE 20
__global__ void __launch_bounds__(STPB)
scatter_kernel(const float* __restrict__ edges,
               const int* __restrict__ snd, const int* __restrict__ rcv) {
    __shared__ __align__(16) float s_v[STPB * SV_STRIDE];
    const int tid = threadIdx.x;
    const int e0 = blockIdx.x * STPB;
    const size_t e = (size_t)e0 + tid;

    float v[F];
#pragma unroll
    for (int f = 0; f < F; f++) v[f] = __ldcs(&edges[(size_t)f * EE + e]);
#pragma unroll
    for (int q = 0; q < 4; q++) {
        float4 w = make_float4(v[q * 4], v[q * 4 + 1], v[q * 4 + 2], v[q * 4 + 3]);
        *reinterpret_cast<float4*>(&s_v[tid * SV_STRIDE + q * 4]) = w;
    }
    __syncthreads();
#pragma unroll
    for (int p = 0; p < 8; p++) {
        int g = tid + p * STPB;
        int chunk = g & 3;
        int which = (g >> 2) & 1;
        int el    = g >> 3;
        int node  = which ? rcv[e0 + el] : snd[e0 + el];
        float* base = which ? g_recv : g_sent;
        float4 w = *reinterpret_cast<const float4*>(&s_v[el * SV_STRIDE + chunk * 4]);
        asm volatile("red.global.add.v4.f32 [%0], {%1,%2,%3,%4};"
                     :: "l"(base + (size_t)node * F + chunk * 4),
                        "f"(w.x), "f"(w.y), "f"(w.z), "f"(w.w)
                     : "memory");
    }
}

// fused node MLP + edge projections + aggregate re-zeroing (prepped weights)
__global__ void __launch_bounds__(256)
node_proj_kernel(const float* src_nodes_in, float* out_nodes) {
    const float* __restrict__ src_nodes = src_nodes_in ? src_nodes_in : g_nodes;
    __shared__ __align__(16) float s_w1t[48 * HID];
    __shared__ __align__(16) float s_w2t[HID * F];
    __shared__ __align__(16) float s_ws[16 * HID];
    __shared__ __align__(16) float s_wr[16 * HID];
    __shared__ __align__(16) float s_b1[HID];
    __shared__ __align__(16) float s_b2[F];
    __shared__ __align__(16) float s_eb1[HID];
    {
        const float4* src;
        float4* dst;
        src = reinterpret_cast<const float4*>(g_nw1t); dst = reinterpret_cast<float4*>(s_w1t);
        for (int i = threadIdx.x; i < (48 * HID) / 4; i += blockDim.x) dst[i] = src[i];
        src = reinterpret_cast<const float4*>(g_nw2t); dst = reinterpret_cast<float4*>(s_w2t);
        for (int i = threadIdx.x; i < (HID * F) / 4; i += blockDim.x) dst[i] = src[i];
        src = reinterpret_cast<const float4*>(g_nws); dst = reinterpret_cast<float4*>(s_ws);
        for (int i = threadIdx.x; i < (16 * HID) / 4; i += blockDim.x) dst[i] = src[i];
        src = reinterpret_cast<const float4*>(g_nwr); dst = reinterpret_cast<float4*>(s_wr);
        for (int i = threadIdx.x; i < (16 * HID) / 4; i += blockDim.x) dst[i] = src[i];
        if (threadIdx.x < HID) { s_b1[threadIdx.x] = g_nb1[threadIdx.x]; s_eb1[threadIdx.x] = g_neb1[threadIdx.x]; }
        if (threadIdx.x < F)   s_b2[threadIdx.x] = g_nb2[threadIdx.x];
    }
    __syncthreads();

    int n = blockIdx.x * blockDim.x + threadIdx.x;
    if (n >= NN) return;

    ull acc[HID / 2];
#pragma unroll
    for (int j = 0; j < HID / 4; j++) {
        ulonglong2 bv = *reinterpret_cast<const ulonglong2*>(&s_b1[j * 4]);
        acc[2 * j] = bv.x; acc[2 * j + 1] = bv.y;
    }
#pragma unroll
    for (int k = 0; k < 16; k++) {
        float xk = src_nodes[(size_t)k * NN + n];
        ull xs = pack2(xk, xk);
        const ulonglong2* w = reinterpret_cast<const ulonglong2*>(&s_w1t[k * HID]);
#pragma unroll
        for (int m = 0; m < 16; m++) {
            ulonglong2 wv = w[m];
            acc[2 * m]     = fma2(wv.x, xs, acc[2 * m]);
            acc[2 * m + 1] = fma2(wv.y, xs, acc[2 * m + 1]);
        }
    }
    const float4 zero4 = make_float4(0.f, 0.f, 0.f, 0.f);
#pragma unroll
    for (int seg = 0; seg < 2; seg++) {
        float* aggr = seg == 0 ? &g_sent[(size_t)n * F] : &g_recv[(size_t)n * F];
        float xv[16];
#pragma unroll
        for (int q = 0; q < 4; q++) {
            float4 v = *reinterpret_cast<const float4*>(&aggr[q * 4]);
            xv[q * 4] = v.x; xv[q * 4 + 1] = v.y; xv[q * 4 + 2] = v.z; xv[q * 4 + 3] = v.w;
            *reinterpret_cast<float4*>(&aggr[q * 4]) = zero4;  // re-zero for next round
        }
#pragma unroll
        for (int k = 0; k < 16; k++) {
            ull xs = pack2(xv[k], xv[k]);
            const ulonglong2* w = reinterpret_cast<const ulonglong2*>(&s_w1t[((seg + 1) * 16 + k) * HID]);
#pragma unroll
            for (int m = 0; m < 16; m++) {
                ulonglong2 wv = w[m];
                acc[2 * m]     = fma2(wv.x, xs, acc[2 * m]);
                acc[2 * m + 1] = fma2(wv.y, xs, acc[2 * m + 1]);
            }
        }
    }

    ull o[F / 2];
#pragma unroll
    for (int j = 0; j < 4; j++) {
        ulonglong2 bv = *reinterpret_cast<const ulonglong2*>(&s_b2[j * 4]);
        o[2 * j] = bv.x; o[2 * j + 1] = bv.y;
    }
#pragma unroll
    for (int h = 0; h < HID; h += 2) {
        float h0, h1; unpack2(acc[h >> 1], h0, h1);
        h0 = fmaxf(h0, 0.f); h1 = fmaxf(h1, 0.f);
        ull x0 = pack2(h0, h0), x1 = pack2(h1, h1);
        const ulonglong2* w0 = reinterpret_cast<const ulonglong2*>(&s_w2t[h * F]);
        const ulonglong2* w1 = reinterpret_cast<const ulonglong2*>(&s_w2t[(h + 1) * F]);
#pragma unroll
        for (int m = 0; m < 4; m++) {
            ulonglong2 a = w0[m], b = w1[m];
            o[2 * m]     = fma2(a.x, x0, o[2 * m]);
            o[2 * m]     = fma2(b.x, x1, o[2 * m]);
            o[2 * m + 1] = fma2(a.y, x0, o[2 * m + 1]);
            o[2 * m + 1] = fma2(b.y, x1, o[2 * m + 1]);
        }
    }
    float y[F];
#pragma unroll
    for (int j = 0; j < F / 2; j++) unpack2(o[j], y[2 * j], y[2 * j + 1]);
#pragma unroll
    for (int k = 0; k < F; k++) {
        g_nodes[(size_t)k * NN + n] = y[k];
    }
    if (out_nodes) {
#pragma unroll
        for (int k = 0; k < F; k++) out_nodes[(size_t)k * NN + n] = y[k];
    }

    // ---- projections from y (fp32 math; fp16 storage scaled by 2^-8) ----
#pragma unroll
    for (int j = 0; j < HID / 4; j++) {
        ulonglong2 bv = *reinterpret_cast<const ulonglong2*>(&s_eb1[j * 4]);
        acc[2 * j] = bv.x; acc[2 * j + 1] = bv.y;
    }
#pragma unroll
    for (int k = 0; k < 16; k++) {
        ull xs = pack2(y[k], y[k]);
        const ulonglong2* w = reinterpret_cast<const ulonglong2*>(&s_ws[k * HID]);
#pragma unroll
        for (int m = 0; m < 16; m++) {
            ulonglong2 wv = w[m];
            acc[2 * m]     = fma2(wv.x, xs, acc[2 * m]);
            acc[2 * m + 1] = fma2(wv.y, xs, acc[2 * m + 1]);
        }
    }
    {
        unsigned int hp[32];
#pragma unroll
        for (int j = 0; j < 32; j++) {
            float a, b; unpack2(acc[j], a, b);
            __half2 h2 = __floats2half2_rn(a * P_SCALE_DOWN, b * P_SCALE_DOWN);
            hp[j] = *reinterpret_cast<unsigned int*>(&h2);
        }
        uint4* outp = reinterpret_cast<uint4*>(&g_ps[(size_t)n * HID]);
#pragma unroll
        for (int j = 0; j < 8; j++)
            outp[j] = make_uint4(hp[4 * j], hp[4 * j + 1], hp[4 * j + 2], hp[4 * j + 3]);
    }

#pragma unroll
    for (int j = 0; j < HID / 2; j++) acc[j] = 0ull;
#pragma unroll
    for (int k = 0; k < 16; k++) {
        ull xs = pack2(y[k], y[k]);
        const ulonglong2* w = reinterpret_cast<const ulonglong2*>(&s_wr[k * HID]);
#pragma unroll
        for (int m = 0; m < 16; m++) {
            ulonglong2 wv = w[m];
            acc[2 * m]     = fma2(wv.x, xs, acc[2 * m]);
            acc[2 * m + 1] = fma2(wv.y, xs, acc[2 * m + 1]);
        }
    }
    {
        unsigned int hp[32];
#pragma unroll
        for (int j = 0; j < 32; j++) {
            float a, b; unpack2(acc[j], a, b);
            __half2 h2 = __floats2half2_rn(a * P_SCALE_DOWN, b * P_SCALE_DOWN);
            hp[j] = *reinterpret_cast<unsigned int*>(&h2);
        }
        uint4* outp = reinterpret_cast<uint4*>(&g_pr[(size_t)n * HID]);
#pragma unroll
        for (int j = 0; j < 8; j++)
            outp[j] = make_uint4(hp[4 * j], hp[4 * j + 1], hp[4 * j + 2], hp[4 * j + 3]);
    }
}

// ---------------- edge MLP v10b: fp16 gather with 2^8 rescale ----------------
#define ETPB 128
#define EPB  128
#define SG_STRIDE 72   // gather row: halves at +0 / +36; also reused as s_out (stride 20)
#define SX_STRIDE 34   // x row per PAIR: [k*2 + half]
#define SO_STRIDE 20   // ov row in reused s_g
#define SG_FLOATS (EPB * SG_STRIDE)
#define SX_FLOATS ((EPB / 2) * SX_STRIDE)
#define EDGE_SMEM_FLOATS (SG_FLOATS + SX_FLOATS + W1_FLOATS + W2_FLOATS + 16)

__global__ void __launch_bounds__(ETPB)
edge_mlp_kernel(const float* src_fe, float* dst_fe,
                const int* __restrict__ snd, const int* __restrict__ rcv,
                int do_scatter) {
    extern __shared__ __align__(16) float smem[];
    float* s_g  = smem;                          // EPB x 72 (split halves); reused as s_out
    float* s_x  = s_g + SG_FLOATS;               // (EPB/2) x 34
    float* s_w1 = s_x + SX_FLOATS;               // 1024, half-interleaved
    float* s_w2 = s_w1 + W1_FLOATS;              // 1024, half-interleaved
    float* s_b2 = s_w2 + W2_FLOATS;              // 16

    const int tid  = threadIdx.x;
    const int half = tid & 1;                    // hidden half: h in [32*half, 32*half+32)
    const int pair = tid >> 1;                   // local pair index
    const int e0   = blockIdx.x * EPB;
    const int ee_l = tid & ~1;                   // even local edge of my pair
    const size_t em = (size_t)e0 + tid;          // my OUTPUT edge

    // ---- load my edge's features (coalesced), stage x into smem
    {
        float x[16];
        if (src_fe) {
#pragma unroll
            for (int k = 0; k < 16; k++) x[k] = __ldcs(&src_fe[(size_t)k * EE + em]);
        } else {
#pragma unroll
            for (int q = 0; q < 4; q++) {
                float4 v = __ldcs(reinterpret_cast<const float4*>(&g_edges[em * F + q * 4]));
                x[q * 4] = v.x; x[q * 4 + 1] = v.y; x[q * 4 + 2] = v.z; x[q * 4 + 3] = v.w;
            }
        }
#pragma unroll
        for (int k = 0; k < 16; k++) s_x[pair * SX_STRIDE + 2 * k + half] = x[k];
    }

    // ---- weights: LINEAR float4 loads from pre-transposed globals (L2-hot)
    {
        const float4* w1s = reinterpret_cast<const float4*>(g_w1p);
        float4*       w1d = reinterpret_cast<float4*>(s_w1);
        for (int i = tid; i < W1_FLOATS / 4; i += ETPB) w1d[i] = w1s[i];
        const float4* w2s = reinterpret_cast<const float4*>(g_w2p);
        float4*       w2d = reinterpret_cast<float4*>(s_w2);
        for (int i = tid; i < W2_FLOATS / 4; i += ETPB) w2d[i] = w2s[i];
        if (tid < 16) s_b2[tid] = g_b2p[tid];
    }

    // ---- cooperative gather staging (scaled fp16 -> fp32, rescale by 2^8)
    //      row = 128 B (64 halves); 8 lanes per row, chunk c = 8 halves (16 B)
    {
        const int wid  = tid >> 5;        // 4 warps, 32 edges each
        const int lane = tid & 31;
        const int sub  = lane >> 3;       // 4 edges per iteration
        const int c    = lane & 7;        // 16B chunk within 128B row
        const int coff = (c < 4) ? c * 8 : 36 + (c - 4) * 8;   // split-layout float offset
#pragma unroll
        for (int i = 0; i < 32; i += 4) {
            int el = wid * 32 + i + sub;
            int s = snd[e0 + el];
            int r = rcv[e0 + el];
            uint4 pa = *reinterpret_cast<const uint4*>(&g_ps[(size_t)s * HID + c * 8]);
            uint4 pb = *reinterpret_cast<const uint4*>(&g_pr[(size_t)r * HID + c * 8]);
            const __half2* ha = reinterpret_cast<const __half2*>(&pa);
            const __half2* hb = reinterpret_cast<const __half2*>(&pb);
            float out[8];
#pragma unroll
            for (int j = 0; j < 4; j++) {
                float2 fa = __half22float2(ha[j]);
                float2 fb = __half22float2(hb[j]);
                out[2 * j]     = (fa.x + fb.x) * P_SCALE_UP;
                out[2 * j + 1] = (fa.y + fb.y) * P_SCALE_UP;
            }
            float* dst = &s_g[el * SG_STRIDE + coff];
            *reinterpret_cast<float4*>(dst)     = make_float4(out[0], out[1], out[2], out[3]);
            *reinterpret_cast<float4*>(dst + 4) = make_float4(out[4], out[5], out[6], out[7]);
        }
    }
    __syncthreads();

    // ---- layer-1 accumulators: my half of BOTH edges (eb1 folded in g_ps)
    ull acc0[16], acc1[16];   // acc0: edge ee_l, acc1: edge ee_l+1
    {
        const ulonglong2* g0 = reinterpret_cast<const ulonglong2*>(&s_g[ee_l * SG_STRIDE + half * 36]);
        const ulonglong2* g1 = reinterpret_cast<const ulonglong2*>(&s_g[(ee_l + 1) * SG_STRIDE + half * 36]);
#pragma unroll
        for (int m = 0; m < 8; m++) {
            ulonglong2 v = g0[m]; acc0[2 * m] = v.x; acc0[2 * m + 1] = v.y;
            ulonglong2 u = g1[m]; acc1[2 * m] = u.x; acc1[2 * m + 1] = u.y;
        }
    }

    // ---- layer 1: one LDS.64 per k gives both edges' x; weights half-interleaved
#pragma unroll
    for (int k = 0; k < 16; k++) {
        float2 xp = *reinterpret_cast<const float2*>(&s_x[pair * SX_STRIDE + 2 * k]);
        ull xs0 = pack2(xp.x, xp.x);     // edge ee_l
        ull xs1 = pack2(xp.y, xp.y);     // edge ee_l+1
#pragma unroll
        for (int m = 0; m < 8; m++) {
            ulonglong2 wv = *reinterpret_cast<const ulonglong2*>(&s_w1[k * 64 + m * 8 + half * 4]);
            acc0[2 * m]     = fma2(wv.x, xs0, acc0[2 * m]);
            acc0[2 * m + 1] = fma2(wv.y, xs0, acc0[2 * m + 1]);
            acc1[2 * m]     = fma2(wv.x, xs1, acc1[2 * m]);
            acc1[2 * m + 1] = fma2(wv.y, xs1, acc1[2 * m + 1]);
        }
    }

    // ---- layer 2 partials over my 32 h (half 0 carries bias for BOTH edges)
    ull o0[8], o1[8];
    if (half == 0) {
#pragma unroll
        for (int j = 0; j < 4; j++) {
            ulonglong2 bv = *reinterpret_cast<const ulonglong2*>(&s_b2[j * 4]);
            o0[2 * j] = bv.x; o0[2 * j + 1] = bv.y;
            o1[2 * j] = bv.x; o1[2 * j + 1] = bv.y;
        }
    } else {
#pragma unroll
        for (int j = 0; j < 8; j++) { o0[j] = 0ull; o1[j] = 0ull; }
    }
#pragma unroll
    for (int it = 0; it < 16; it++) {
        float a0, a1; unpack2(acc0[it], a0, a1);
        a0 = fmaxf(a0, 0.f); a1 = fmaxf(a1, 0.f);
        ull p00 = pack2(a0, a0), p01 = pack2(a1, a1);
        float b0, b1; unpack2(acc1[it], b0, b1);
        b0 = fmaxf(b0, 0.f); b1 = fmaxf(b1, 0.f);
        ull p10 = pack2(b0, b0), p11 = pack2(b1, b1);
#pragma unroll
        for (int m = 0; m < 4; m++) {
            ulonglong2 a = *reinterpret_cast<const ulonglong2*>(&s_w2[(2 * it) * 32 + m * 8 + half * 4]);
            ulonglong2 b = *reinterpret_cast<const ulonglong2*>(&s_w2[(2 * it + 1) * 32 + m * 8 + half * 4]);
            o0[2 * m]     = fma2(a.x, p00, o0[2 * m]);
            o0[2 * m]     = fma2(b.x, p01, o0[2 * m]);
            o0[2 * m + 1] = fma2(a.y, p00, o0[2 * m + 1]);
            o0[2 * m + 1] = fma2(b.y, p01, o0[2 * m + 1]);
            o1[2 * m]     = fma2(a.x, p10, o1[2 * m]);
            o1[2 * m]     = fma2(b.x, p11, o1[2 * m]);
            o1[2 * m + 1] = fma2(a.y, p10, o1[2 * m + 1]);
            o1[2 * m + 1] = fma2(b.y, p11, o1[2 * m + 1]);
        }
    }

    // ---- single exchange: send partner's-edge partial, receive mine
    float ov[16];
#pragma unroll
    for (int j = 0; j < 8; j++) {
        ull sel  = half ? o0[j] : o1[j];            // partial for PARTNER's edge
        ull rec  = __shfl_xor_sync(0xFFFFFFFFu, sel, 1);
        ull mine = half ? o1[j] : o0[j];            // my partial for MY edge
        ull tot  = add2(mine, rec);
        unpack2(tot, ov[2 * j], ov[2 * j + 1]);
    }

    // ---- write my edge's new features
    if (dst_fe) {
#pragma unroll
        for (int f = 0; f < F; f++) __stcs(&dst_fe[(size_t)f * EE + em], ov[f]);
    } else {
#pragma unroll
        for (int q = 0; q < 4; q++) {
            float4 v = make_float4(ov[q * 4], ov[q * 4 + 1], ov[q * 4 + 2], ov[q * 4 + 3]);
            __stcs(reinterpret_cast<float4*>(&g_edges[em * F + q * 4]), v);
        }
    }

    // ---- cooperative red phase: 4 lanes cover one edge's 64B row -> 1 line
    if (do_scatter) {
        float* s_out = s_g;                       // staging buffer is dead; reuse
        __syncthreads();
#pragma unroll
        for (int q = 0; q < 4; q++) {
            float4 v = make_float4(ov[q * 4], ov[q * 4 + 1], ov[q * 4 + 2], ov[q * 4 + 3]);
            *reinterpret_cast<float4*>(&s_out[tid * SO_STRIDE + q * 4]) = v;
        }
        __syncthreads();
#pragma unroll
        for (int p = 0; p < 8; p++) {
            int g = tid + p * ETPB;
            int chunk = g & 3;
            int which = (g >> 2) & 1;
            int el    = g >> 3;
            int node  = which ? rcv[e0 + el] : snd[e0 + el];
            float* base = which ? g_recv : g_sent;
            float4 v = *reinterpret_cast<const float4*>(&s_out[el * SO_STRIDE + chunk * 4]);
            asm volatile("red.global.add.v4.f32 [%0], {%1,%2,%3,%4};"
                         :: "l"(base + (size_t)node * F + chunk * 4),
                            "f"(v.x), "f"(v.y), "f"(v.z), "f"(v.w)
                         : "memory");
        }
    }
}

extern "C" void kernel_launch(void* const* d_in, const int* in_sizes, int n_in,
                              void* d_out, int out_size) {
    const float* nodes     = (const float*)d_in[0];
    const float* edges     = (const float*)d_in[1];
    const int*   receivers = (const int*)  d_in[2];
    const int*   senders   = (const int*)  d_in[3];
    const float* nW1 = (const float*)d_in[4];
    const float* nb1 = (const float*)d_in[5];
    const float* nW2 = (const float*)d_in[6];
    const float* nb2 = (const float*)d_in[7];
    const float* eW1 = (const float*)d_in[8];
    const float* eb1 = (const float*)d_in[9];
    const float* eW2 = (const float*)d_in[10];
    const float* eb2 = (const float*)d_in[11];
    float* out_nodes = (float*)d_out;
    float* out_edges = (float*)d_out + (size_t)F * NN;

    const int EDGE_BLOCKS = EE / EPB;                  // 25000
    const int NODE_BLOCKS = (NN + 255) / 256;          // 391
    const int ZERO_BLOCKS = ((NN * F) / 4 + 255) / 256;
    const int EDGE_SMEM = EDGE_SMEM_FLOATS * 4;        // ~53.8 KB

    static int configured = 0;
    if (!configured) {
        cudaFuncSetAttribute(edge_mlp_kernel, cudaFuncAttributeMaxDynamicSharedMemorySize, EDGE_SMEM);
        configured = 1;
    }

    prep_weights_kernel<<<1, 256>>>(eW1, eW2, eb2, nW1, nb1, nW2, nb2, eb1);
    zero_agg_kernel<<<ZERO_BLOCKS, 256>>>();
    scatter_kernel<<<EE / STPB, STPB>>>(edges, senders, receivers);

    for (int round = 0; round < ROUNDS; round++) {
        node_proj_kernel<<<NODE_BLOCKS, 256>>>(
            (round == 0) ? nodes : (const float*)0,
            (round == ROUNDS - 1) ? out_nodes : (float*)0);
        edge_mlp_kernel<<<EDGE_BLOCKS, ETPB, EDGE_SMEM>>>(
            (round == 0) ? edges : (const float*)0,
            (round == ROUNDS - 1) ? out_edges : (float*)0,
            senders, receivers, (round < ROUNDS - 1) ? 1 : 0);
    }
}